// round 2
// baseline (speedup 1.0000x reference)
#include <cuda_runtime.h>

// ---------------- problem constants ----------------
#define BB 2
#define TT 24
#define NN 512
#define DD 512
#define NH 8
#define HD 64
#define MROWS (BB*TT*NN)      // 24576
#define C3 3072               // P row stride: [sQ sK sV tQ tK tV]

// ---------------- scratch (static device globals; no allocation) ----------------
__device__ float g_Xc [(size_t)MROWS * 1536];   // concat(X, STE)
__device__ float g_P  [(size_t)MROWS * 3072];   // all six projections, relu'd
__device__ float g_Wcat[1536 * 3072];
__device__ float g_bcat[3072];
__device__ float g_Wg  [1024 * 512];
__device__ float g_HS [(size_t)MROWS * 512];    // spatial attn out -> Zlin -> H2
__device__ float g_HT [(size_t)MROWS * 512];    // temporal attn out -> H1
__device__ float g_HST[(size_t)MROWS * 1024];   // [HS_proj | HT_proj]

// ---------------- concat kernels ----------------
__global__ void concat_xc_k(const float* __restrict__ X, const float* __restrict__ STE,
                            float* __restrict__ Xc)
{
    int idx = blockIdx.x * blockDim.x + threadIdx.x;   // float4 units
    if (idx >= MROWS * 384) return;
    int m = idx / 384, c4 = idx % 384;
    float4 v;
    if (c4 < 128) v = ((const float4*)X)[(size_t)m * 128 + c4];
    else          v = ((const float4*)STE)[(size_t)m * 256 + (c4 - 128)];
    ((float4*)Xc)[idx] = v;
}

__global__ void concat_w_k(const float* __restrict__ w0, const float* __restrict__ w1,
                           const float* __restrict__ w2, const float* __restrict__ w3,
                           const float* __restrict__ w4, const float* __restrict__ w5,
                           const float* __restrict__ b0, const float* __restrict__ b1,
                           const float* __restrict__ b2, const float* __restrict__ b3,
                           const float* __restrict__ b4, const float* __restrict__ b5,
                           float* __restrict__ Wc, float* __restrict__ bc)
{
    int idx = blockIdx.x * blockDim.x + threadIdx.x;
    if (idx < 1536 * 3072) {
        int k = idx / 3072, n = idx % 3072;
        int j = n >> 9, c = n & 511;
        const float* ws[6] = {w0, w1, w2, w3, w4, w5};
        Wc[idx] = ws[j][k * 512 + c];
    }
    if (idx < 3072) {
        int j = idx >> 9, c = idx & 511;
        const float* bs[6] = {b0, b1, b2, b3, b4, b5};
        bc[idx] = bs[j][c];
    }
}

__global__ void concat_wg_k(const float* __restrict__ wxs, const float* __restrict__ wxt,
                            float* __restrict__ Wg)
{
    int idx = blockIdx.x * blockDim.x + threadIdx.x;
    if (idx >= 1024 * 512) return;
    int k = idx / 512, c = idx % 512;
    Wg[idx] = (k < 512) ? wxs[k * 512 + c] : wxt[(k - 512) * 512 + c];
}

// ---------------- tiled SGEMM 128x128x8, bias + activation epilogue ----------------
// ACT: 0 = bias only, 1 = bias + relu, 2 = bias + residual add
template<int ACT>
__global__ void __launch_bounds__(256) sgemm_k(
    const float* __restrict__ A, const float* __restrict__ B,
    const float* __restrict__ bias, const float* __restrict__ R,
    float* __restrict__ C, int M, int N, int K, int lda, int ldb, int ldc)
{
    __shared__ float As[8][132];
    __shared__ float Bs[8][132];
    const int tid = threadIdx.x;
    const int m0 = blockIdx.y * 128;
    const int n0 = blockIdx.x * 128;
    const int tx = tid & 15;
    const int ty = tid >> 4;
    const int a_row = tid >> 1;
    const int a_col = (tid & 1) << 2;
    const int b_row = tid >> 5;
    const int b_col = (tid & 31) << 2;

    const float* Ap = A + (size_t)(m0 + a_row) * lda + a_col;
    const float* Bp = B + (size_t)b_row * ldb + n0 + b_col;

    float acc[8][8];
#pragma unroll
    for (int i = 0; i < 8; i++)
#pragma unroll
        for (int j = 0; j < 8; j++) acc[i][j] = 0.f;

    for (int k0 = 0; k0 < K; k0 += 8) {
        float4 va = *(const float4*)(Ap + k0);
        float4 vb = *(const float4*)(Bp + (size_t)k0 * ldb);
        As[a_col + 0][a_row] = va.x;
        As[a_col + 1][a_row] = va.y;
        As[a_col + 2][a_row] = va.z;
        As[a_col + 3][a_row] = va.w;
        *(float4*)&Bs[b_row][b_col] = vb;
        __syncthreads();
#pragma unroll
        for (int kk = 0; kk < 8; kk++) {
            float a0[4], a1[4], b0[4], b1[4];
            *(float4*)a0 = *(const float4*)&As[kk][ty * 4];
            *(float4*)a1 = *(const float4*)&As[kk][64 + ty * 4];
            *(float4*)b0 = *(const float4*)&Bs[kk][tx * 4];
            *(float4*)b1 = *(const float4*)&Bs[kk][64 + tx * 4];
#pragma unroll
            for (int i = 0; i < 4; i++)
#pragma unroll
                for (int j = 0; j < 4; j++) {
                    acc[i][j]         += a0[i] * b0[j];
                    acc[i][j + 4]     += a0[i] * b1[j];
                    acc[i + 4][j]     += a1[i] * b0[j];
                    acc[i + 4][j + 4] += a1[i] * b1[j];
                }
        }
        __syncthreads();
    }

    float4 bv0 = *(const float4*)(bias + n0 + tx * 4);
    float4 bv1 = *(const float4*)(bias + n0 + 64 + tx * 4);
    float bb0[4] = {bv0.x, bv0.y, bv0.z, bv0.w};
    float bb1[4] = {bv1.x, bv1.y, bv1.z, bv1.w};

#pragma unroll
    for (int i = 0; i < 8; i++) {
        int row = m0 + ((i < 4) ? (ty * 4 + i) : (64 + ty * 4 + (i - 4)));
        float out0[4], out1[4];
#pragma unroll
        for (int j = 0; j < 4; j++) {
            out0[j] = acc[i][j] + bb0[j];
            out1[j] = acc[i][j + 4] + bb1[j];
        }
        if (ACT == 1) {
#pragma unroll
            for (int j = 0; j < 4; j++) {
                out0[j] = fmaxf(out0[j], 0.f);
                out1[j] = fmaxf(out1[j], 0.f);
            }
        }
        if (ACT == 2) {
            float4 r0 = *(const float4*)(R + (size_t)row * ldc + n0 + tx * 4);
            float4 r1 = *(const float4*)(R + (size_t)row * ldc + n0 + 64 + tx * 4);
            out0[0] += r0.x; out0[1] += r0.y; out0[2] += r0.z; out0[3] += r0.w;
            out1[0] += r1.x; out1[1] += r1.y; out1[2] += r1.z; out1[3] += r1.w;
        }
        *(float4*)(C + (size_t)row * ldc + n0 + tx * 4)      = make_float4(out0[0], out0[1], out0[2], out0[3]);
        *(float4*)(C + (size_t)row * ldc + n0 + 64 + tx * 4) = make_float4(out1[0], out1[1], out1[2], out1[3]);
    }
}

// ---------------- spatial attention: flash-style, 1 query row per thread ----------------
// grid: B*T*NH*2 blocks, 256 threads. Each block: one (b,t,head), 256 query rows.
__global__ void __launch_bounds__(256) spatial_attn_k(const float* __restrict__ P,
                                                      float* __restrict__ HS)
{
    const int bid  = blockIdx.x;
    const int half = bid & 1;
    const int h    = (bid >> 1) & 7;
    const int bt   = bid >> 4;               // 0..47
    const int n    = half * 256 + threadIdx.x;
    const float* base = P + (size_t)bt * NN * C3;

    float q[64];
    {
        const float4* qp = (const float4*)(base + (size_t)n * C3 + h * HD);
#pragma unroll
        for (int i = 0; i < 16; i++) {
            float4 v = qp[i];
            q[4 * i] = v.x; q[4 * i + 1] = v.y; q[4 * i + 2] = v.z; q[4 * i + 3] = v.w;
        }
    }
    float o[64];
#pragma unroll
    for (int i = 0; i < 64; i++) o[i] = 0.f;
    float mr = -1e30f, l = 0.f;

    __shared__ float4 Ks[64][16];
    __shared__ float4 Vs[64][16];

    for (int m0 = 0; m0 < NN; m0 += 64) {
        __syncthreads();
#pragma unroll
        for (int i = 0; i < 4; i++) {
            int pos = threadIdx.x + i * 256;
            int row = pos >> 4, c4 = pos & 15;
            const float* kr = base + (size_t)(m0 + row) * C3 + 512 + h * HD;
            const float* vr = base + (size_t)(m0 + row) * C3 + 1024 + h * HD;
            Ks[row][c4] = *(const float4*)(kr + c4 * 4);
            Vs[row][c4] = *(const float4*)(vr + c4 * 4);
        }
        __syncthreads();

        for (int j = 0; j < 64; j++) {
            float s0 = 0.f, s1 = 0.f, s2 = 0.f, s3 = 0.f;
#pragma unroll
            for (int c = 0; c < 16; c++) {
                float4 kk = Ks[j][c];
                s0 += q[4 * c]     * kk.x;
                s1 += q[4 * c + 1] * kk.y;
                s2 += q[4 * c + 2] * kk.z;
                s3 += q[4 * c + 3] * kk.w;
            }
            float s = ((s0 + s1) + (s2 + s3)) * 0.125f;
            if (s <= mr) {
                float p = __expf(s - mr);
                l += p;
#pragma unroll
                for (int c = 0; c < 16; c++) {
                    float4 vv = Vs[j][c];
                    o[4 * c]     += p * vv.x;
                    o[4 * c + 1] += p * vv.y;
                    o[4 * c + 2] += p * vv.z;
                    o[4 * c + 3] += p * vv.w;
                }
            } else {
                float r = __expf(mr - s);
                mr = s;
                l = l * r + 1.f;
#pragma unroll
                for (int c = 0; c < 16; c++) {
                    float4 vv = Vs[j][c];
                    o[4 * c]     = o[4 * c]     * r + vv.x;
                    o[4 * c + 1] = o[4 * c + 1] * r + vv.y;
                    o[4 * c + 2] = o[4 * c + 2] * r + vv.z;
                    o[4 * c + 3] = o[4 * c + 3] * r + vv.w;
                }
            }
        }
    }
    float inv = 1.f / l;
    float4* op = (float4*)(HS + (size_t)(bt * NN + n) * 512 + h * HD);
#pragma unroll
    for (int i = 0; i < 16; i++)
        op[i] = make_float4(o[4 * i] * inv, o[4 * i + 1] * inv,
                            o[4 * i + 2] * inv, o[4 * i + 3] * inv);
}

// ---------------- temporal attention (causal over T=24) ----------------
// grid (NN, BB), 192 threads: thread = (t, head). K/V streamed through L1.
__global__ void __launch_bounds__(192) temporal_attn_k(const float* __restrict__ P,
                                                       float* __restrict__ HT)
{
    const int n = blockIdx.x;
    const int b = blockIdx.y;
    const int h = threadIdx.x & 7;
    const int t = threadIdx.x >> 3;          // 0..23

    float q[64];
    {
        const float4* qp = (const float4*)(P + ((size_t)(b * TT + t) * NN + n) * C3 + 1536 + h * HD);
#pragma unroll
        for (int i = 0; i < 16; i++) {
            float4 v = __ldg(qp + i);
            q[4 * i] = v.x; q[4 * i + 1] = v.y; q[4 * i + 2] = v.z; q[4 * i + 3] = v.w;
        }
    }
    float o[64];
#pragma unroll
    for (int i = 0; i < 64; i++) o[i] = 0.f;
    float mr = -1e30f, l = 0.f;

    for (int s = 0; s <= t; s++) {
        size_t rk = ((size_t)(b * TT + s) * NN + n) * C3;
        const float4* kp = (const float4*)(P + rk + 2048 + h * HD);
        const float4* vp = (const float4*)(P + rk + 2560 + h * HD);
        float s0 = 0.f, s1 = 0.f, s2 = 0.f, s3 = 0.f;
#pragma unroll
        for (int c = 0; c < 16; c++) {
            float4 kk = __ldg(kp + c);
            s0 += q[4 * c]     * kk.x;
            s1 += q[4 * c + 1] * kk.y;
            s2 += q[4 * c + 2] * kk.z;
            s3 += q[4 * c + 3] * kk.w;
        }
        float sc = ((s0 + s1) + (s2 + s3)) * 0.125f;
        if (sc <= mr) {
            float p = __expf(sc - mr);
            l += p;
#pragma unroll
            for (int c = 0; c < 16; c++) {
                float4 vv = __ldg(vp + c);
                o[4 * c]     += p * vv.x;
                o[4 * c + 1] += p * vv.y;
                o[4 * c + 2] += p * vv.z;
                o[4 * c + 3] += p * vv.w;
            }
        } else {
            float r = __expf(mr - sc);
            mr = sc;
            l = l * r + 1.f;
#pragma unroll
            for (int c = 0; c < 16; c++) {
                float4 vv = __ldg(vp + c);
                o[4 * c]     = o[4 * c]     * r + vv.x;
                o[4 * c + 1] = o[4 * c + 1] * r + vv.y;
                o[4 * c + 2] = o[4 * c + 2] * r + vv.z;
                o[4 * c + 3] = o[4 * c + 3] * r + vv.w;
            }
        }
    }
    float inv = 1.f / l;
    float4* op = (float4*)(HT + ((size_t)(b * TT + t) * NN + n) * 512 + h * HD);
#pragma unroll
    for (int i = 0; i < 16; i++)
        op[i] = make_float4(o[4 * i] * inv, o[4 * i + 1] * inv,
                            o[4 * i + 2] * inv, o[4 * i + 3] * inv);
}

// ---------------- gated fusion elementwise ----------------
__global__ void gate_k(const float* __restrict__ Zl, const float* __restrict__ HST,
                       float* __restrict__ H1)
{
    int idx = blockIdx.x * blockDim.x + threadIdx.x;    // float4 units over M*128
    if (idx >= MROWS * 128) return;
    int m = idx >> 7, c4 = idx & 127;
    float4 zl = ((const float4*)Zl)[idx];
    const float4* row = (const float4*)(HST + (size_t)m * 1024);
    float4 hs = row[c4];
    float4 ht = row[128 + c4];
    float zx = 1.f / (1.f + __expf(-zl.x));
    float zy = 1.f / (1.f + __expf(-zl.y));
    float zz = 1.f / (1.f + __expf(-zl.z));
    float zw = 1.f / (1.f + __expf(-zl.w));
    float4 out;
    out.x = zx * hs.x + (1.f - zx) * ht.x;
    out.y = zy * hs.y + (1.f - zy) * ht.y;
    out.z = zz * hs.z + (1.f - zz) * ht.z;
    out.w = zw * hs.w + (1.f - zw) * ht.w;
    ((float4*)H1)[idx] = out;
}

// ---------------- launch ----------------
extern "C" void kernel_launch(void* const* d_in, const int* in_sizes, int n_in,
                              void* d_out, int out_size)
{
    const float* X    = (const float*)d_in[0];
    const float* STE  = (const float*)d_in[1];
    const float* sWq  = (const float*)d_in[2];
    const float* sbq  = (const float*)d_in[3];
    const float* sWk  = (const float*)d_in[4];
    const float* sbk  = (const float*)d_in[5];
    const float* sWv  = (const float*)d_in[6];
    const float* sbv  = (const float*)d_in[7];
    const float* sWo  = (const float*)d_in[8];
    const float* sbo  = (const float*)d_in[9];
    const float* tWq  = (const float*)d_in[10];
    const float* tbq  = (const float*)d_in[11];
    const float* tWk  = (const float*)d_in[12];
    const float* tbk  = (const float*)d_in[13];
    const float* tWv  = (const float*)d_in[14];
    const float* tbv  = (const float*)d_in[15];
    const float* tWo  = (const float*)d_in[16];
    const float* tbo  = (const float*)d_in[17];
    const float* gWxs = (const float*)d_in[18];
    const float* gWxt = (const float*)d_in[19];
    const float* gbxt = (const float*)d_in[20];
    const float* gWh1 = (const float*)d_in[21];
    const float* gbh1 = (const float*)d_in[22];
    const float* gWh2 = (const float*)d_in[23];
    const float* gbh2 = (const float*)d_in[24];
    float* out = (float*)d_out;

    float *Xc, *P, *Wcat, *bcat, *Wg, *HS, *HT, *HST;
    cudaGetSymbolAddress((void**)&Xc,   g_Xc);
    cudaGetSymbolAddress((void**)&P,    g_P);
    cudaGetSymbolAddress((void**)&Wcat, g_Wcat);
    cudaGetSymbolAddress((void**)&bcat, g_bcat);
    cudaGetSymbolAddress((void**)&Wg,   g_Wg);
    cudaGetSymbolAddress((void**)&HS,   g_HS);
    cudaGetSymbolAddress((void**)&HT,   g_HT);
    cudaGetSymbolAddress((void**)&HST,  g_HST);

    // 1) build Xc = [X | STE]  and concatenated weights
    concat_xc_k<<<(MROWS * 384 + 255) / 256, 256>>>(X, STE, Xc);
    concat_w_k<<<(1536 * 3072 + 255) / 256, 256>>>(sWq, sWk, sWv, tWq, tWk, tWv,
                                                   sbq, sbk, sbv, tbq, tbk, tbv,
                                                   Wcat, bcat);
    concat_wg_k<<<(1024 * 512 + 255) / 256, 256>>>(gWxs, gWxt, Wg);

    // 2) all six projections in one GEMM (relu epilogue): P = relu(Xc @ Wcat + bcat)
    sgemm_k<1><<<dim3(3072 / 128, MROWS / 128), 256>>>(Xc, Wcat, bcat, nullptr, P,
                                                       MROWS, 3072, 1536, 1536, 3072, 3072);

    // 3) attention
    spatial_attn_k<<<BB * TT * NH * 2, 256>>>(P, HS);
    temporal_attn_k<<<dim3(NN, BB), 192>>>(P, HT);

    // 4) output projections into HST = [relu(HS@sWo+b) | relu(HT@tWo+b)]
    sgemm_k<1><<<dim3(4, MROWS / 128), 256>>>(HS, sWo, sbo, nullptr, HST,
                                              MROWS, 512, 512, 512, 512, 1024);
    sgemm_k<1><<<dim3(4, MROWS / 128), 256>>>(HT, tWo, tbo, nullptr, HST + 512,
                                              MROWS, 512, 512, 512, 512, 1024);

    // 5) gate: Zlin = HST @ [gWxs; gWxt] + gbxt  (stored into HS buffer)
    sgemm_k<0><<<dim3(4, MROWS / 128), 256>>>(HST, Wg, gbxt, nullptr, HS,
                                              MROWS, 512, 1024, 1024, 512, 512);
    // H1 = sigmoid(Zlin)*HSp + (1-sigmoid)*HTp   (stored into HT buffer)
    gate_k<<<(MROWS * 128 + 255) / 256, 256>>>(HS, HST, HT);

    // 6) MLP: H2 = relu(H1 @ gWh1 + gbh1)  (into HS buffer)
    sgemm_k<1><<<dim3(4, MROWS / 128), 256>>>(HT, gWh1, gbh1, nullptr, HS,
                                              MROWS, 512, 512, 512, 512, 512);
    // out = X + H2 @ gWh2 + gbh2
    sgemm_k<2><<<dim3(4, MROWS / 128), 256>>>(HS, gWh2, gbh2, X, out,
                                              MROWS, 512, 512, 512, 512, 512);
}

// round 3
// speedup vs baseline: 1.2866x; 1.2866x over previous
#include <cuda_runtime.h>
#include <mma.h>
using namespace nvcuda;

// ---------------- problem constants ----------------
#define BB 2
#define TT 24
#define NN 512
#define DD 512
#define NH 8
#define HD 64
#define MROWS (BB*TT*NN)      // 24576
#define C3 3072               // P row stride: [sQ sK sV tQ tK tV]

// ---------------- scratch (static device globals; no allocation) ----------------
__device__ float g_Xc [(size_t)MROWS * 1536];   // concat(X, STE)
__device__ float g_P  [(size_t)MROWS * 3072];   // all six projections, relu'd
__device__ float g_Wcat[1536 * 3072];
__device__ float g_bcat[3072];
__device__ float g_Wg  [1024 * 512];
__device__ float g_HS [(size_t)MROWS * 512];
__device__ float g_HT [(size_t)MROWS * 512];
__device__ float g_HST[(size_t)MROWS * 1024];

// ---------------- concat kernels ----------------
__global__ void concat_xc_k(const float* __restrict__ X, const float* __restrict__ STE,
                            float* __restrict__ Xc)
{
    int idx = blockIdx.x * blockDim.x + threadIdx.x;   // float4 units
    if (idx >= MROWS * 384) return;
    int m = idx / 384, c4 = idx % 384;
    float4 v;
    if (c4 < 128) v = ((const float4*)X)[(size_t)m * 128 + c4];
    else          v = ((const float4*)STE)[(size_t)m * 256 + (c4 - 128)];
    ((float4*)Xc)[idx] = v;
}

__global__ void concat_w_k(const float* __restrict__ w0, const float* __restrict__ w1,
                           const float* __restrict__ w2, const float* __restrict__ w3,
                           const float* __restrict__ w4, const float* __restrict__ w5,
                           const float* __restrict__ b0, const float* __restrict__ b1,
                           const float* __restrict__ b2, const float* __restrict__ b3,
                           const float* __restrict__ b4, const float* __restrict__ b5,
                           float* __restrict__ Wc, float* __restrict__ bc)
{
    int idx = blockIdx.x * blockDim.x + threadIdx.x;
    if (idx < 1536 * 3072) {
        int k = idx / 3072, n = idx % 3072;
        int j = n >> 9, c = n & 511;
        const float* ws[6] = {w0, w1, w2, w3, w4, w5};
        Wc[idx] = ws[j][k * 512 + c];
    }
    if (idx < 3072) {
        int j = idx >> 9, c = idx & 511;
        const float* bs[6] = {b0, b1, b2, b3, b4, b5};
        bc[idx] = bs[j][c];
    }
}

__global__ void concat_wg_k(const float* __restrict__ wxs, const float* __restrict__ wxt,
                            float* __restrict__ Wg)
{
    int idx = blockIdx.x * blockDim.x + threadIdx.x;
    if (idx >= 1024 * 512) return;
    int k = idx / 512, c = idx % 512;
    Wg[idx] = (k < 512) ? wxs[k * 512 + c] : wxt[(k - 512) * 512 + c];
}

// ---------------- tf32 tensor-core GEMM 128x128, BK=16 double-buffered ----------------
// ACT: 0 = bias only, 1 = bias + relu, 2 = bias + residual add
// Requires: M%128==0, N%128==0, K%16==0.
#define A_LD 24
#define B_LD 136
#define AS_STRIDE (128 * A_LD)   // 3072 floats per buffer
#define BS_STRIDE (16 * B_LD)    // 2176 floats per buffer

template<int ACT>
__global__ void __launch_bounds__(256, 2) gemm_tf32_k(
    const float* __restrict__ A, const float* __restrict__ B,
    const float* __restrict__ bias, const float* __restrict__ R,
    float* __restrict__ C, int M, int N, int K, int lda, int ldb, int ldc)
{
    __shared__ float smem[2 * AS_STRIDE + 2 * BS_STRIDE];   // 41984 B
    float* As = smem;
    float* Bs = smem + 2 * AS_STRIDE;

    const int tid  = threadIdx.x;
    const int warp = tid >> 5;
    const int lane = tid & 31;
    const int wm   = warp & 3;    // M subtile (32 rows each)
    const int wn   = warp >> 2;   // N subtile (64 cols each)
    const int m0 = blockIdx.y * 128;
    const int n0 = blockIdx.x * 128;

    // global->smem load mapping
    const int a_row = tid >> 2;          // 0..63 (two passes cover 128 rows)
    const int a_c4  = (tid & 3) << 2;    // 0,4,8,12
    const int b_row = tid >> 5;          // 0..7 (two passes cover 16 rows)
    const int b_c4  = (tid & 31) << 2;   // 0..124

    wmma::fragment<wmma::accumulator, 16, 16, 8, float> acc[2][4];
#pragma unroll
    for (int i = 0; i < 2; i++)
#pragma unroll
        for (int j = 0; j < 4; j++) wmma::fill_fragment(acc[i][j], 0.f);

    // preload tile 0
    {
        float4 va0 = *(const float4*)(A + (size_t)(m0 + a_row) * lda + a_c4);
        float4 va1 = *(const float4*)(A + (size_t)(m0 + 64 + a_row) * lda + a_c4);
        float4 vb0 = *(const float4*)(B + (size_t)b_row * ldb + n0 + b_c4);
        float4 vb1 = *(const float4*)(B + (size_t)(8 + b_row) * ldb + n0 + b_c4);
        *(float4*)(As + a_row * A_LD + a_c4)        = va0;
        *(float4*)(As + (64 + a_row) * A_LD + a_c4) = va1;
        *(float4*)(Bs + b_row * B_LD + b_c4)        = vb0;
        *(float4*)(Bs + (8 + b_row) * B_LD + b_c4)  = vb1;
    }
    __syncthreads();

    const int nk = K >> 4;
    for (int kt = 0; kt < nk; kt++) {
        const int buf = kt & 1;
        float4 pa0, pa1, pb0, pb1;
        const bool pref = (kt + 1 < nk);
        if (pref) {
            int k0 = (kt + 1) << 4;
            pa0 = *(const float4*)(A + (size_t)(m0 + a_row) * lda + k0 + a_c4);
            pa1 = *(const float4*)(A + (size_t)(m0 + 64 + a_row) * lda + k0 + a_c4);
            pb0 = *(const float4*)(B + (size_t)(k0 + b_row) * ldb + n0 + b_c4);
            pb1 = *(const float4*)(B + (size_t)(k0 + 8 + b_row) * ldb + n0 + b_c4);
        }

        const float* Ab = As + buf * AS_STRIDE;
        const float* Bb = Bs + buf * BS_STRIDE;
#pragma unroll
        for (int ks = 0; ks < 2; ks++) {
            wmma::fragment<wmma::matrix_a, 16, 16, 8, wmma::precision::tf32, wmma::row_major> af[2];
            wmma::fragment<wmma::matrix_b, 16, 16, 8, wmma::precision::tf32, wmma::row_major> bf[4];
#pragma unroll
            for (int fm = 0; fm < 2; fm++) {
                wmma::load_matrix_sync(af[fm], Ab + (wm * 32 + fm * 16) * A_LD + ks * 8, A_LD);
#pragma unroll
                for (int e = 0; e < af[fm].num_elements; e++)
                    af[fm].x[e] = wmma::__float_to_tf32(af[fm].x[e]);
            }
#pragma unroll
            for (int fn = 0; fn < 4; fn++) {
                wmma::load_matrix_sync(bf[fn], Bb + (ks * 8) * B_LD + wn * 64 + fn * 16, B_LD);
#pragma unroll
                for (int e = 0; e < bf[fn].num_elements; e++)
                    bf[fn].x[e] = wmma::__float_to_tf32(bf[fn].x[e]);
            }
#pragma unroll
            for (int fm = 0; fm < 2; fm++)
#pragma unroll
                for (int fn = 0; fn < 4; fn++)
                    wmma::mma_sync(acc[fm][fn], af[fm], bf[fn], acc[fm][fn]);
        }

        if (pref) {
            float* An = As + (buf ^ 1) * AS_STRIDE;
            float* Bn = Bs + (buf ^ 1) * BS_STRIDE;
            *(float4*)(An + a_row * A_LD + a_c4)        = pa0;
            *(float4*)(An + (64 + a_row) * A_LD + a_c4) = pa1;
            *(float4*)(Bn + b_row * B_LD + b_c4)        = pb0;
            *(float4*)(Bn + (8 + b_row) * B_LD + b_c4)  = pb1;
        }
        __syncthreads();
    }

    // epilogue: per-warp smem scratch (32 rows x 40 stride), two 32-col halves
    float* sw = smem + warp * (32 * 40);
#pragma unroll
    for (int h = 0; h < 2; h++) {
#pragma unroll
        for (int fm = 0; fm < 2; fm++)
#pragma unroll
            for (int fnl = 0; fnl < 2; fnl++)
                wmma::store_matrix_sync(sw + fm * 16 * 40 + fnl * 16,
                                        acc[fm][h * 2 + fnl], 40, wmma::mem_row_major);
        __syncwarp();
        const int colbase = n0 + wn * 64 + h * 32;
#pragma unroll
        for (int i = 0; i < 8; i++) {
            int idx = lane + i * 32;        // 0..255
            int r  = idx >> 3;              // 0..31
            int c4 = (idx & 7) << 2;        // 0..28
            float4 v = *(float4*)(sw + r * 40 + c4);
            int row = m0 + wm * 32 + r;
            int col = colbase + c4;
            float4 bv = *(const float4*)(bias + col);
            v.x += bv.x; v.y += bv.y; v.z += bv.z; v.w += bv.w;
            if (ACT == 1) {
                v.x = fmaxf(v.x, 0.f); v.y = fmaxf(v.y, 0.f);
                v.z = fmaxf(v.z, 0.f); v.w = fmaxf(v.w, 0.f);
            }
            if (ACT == 2) {
                float4 rv = *(const float4*)(R + (size_t)row * ldc + col);
                v.x += rv.x; v.y += rv.y; v.z += rv.z; v.w += rv.w;
            }
            *(float4*)(C + (size_t)row * ldc + col) = v;
        }
        __syncwarp();
    }
}

// ---------------- spatial attention: flash-style, 1 query row per thread ----------------
__global__ void __launch_bounds__(256) spatial_attn_k(const float* __restrict__ P,
                                                      float* __restrict__ HS)
{
    const int bid  = blockIdx.x;
    const int half = bid & 1;
    const int h    = (bid >> 1) & 7;
    const int bt   = bid >> 4;               // 0..47
    const int n    = half * 256 + threadIdx.x;
    const float* base = P + (size_t)bt * NN * C3;

    float q[64];
    {
        const float4* qp = (const float4*)(base + (size_t)n * C3 + h * HD);
#pragma unroll
        for (int i = 0; i < 16; i++) {
            float4 v = qp[i];
            q[4 * i] = v.x; q[4 * i + 1] = v.y; q[4 * i + 2] = v.z; q[4 * i + 3] = v.w;
        }
    }
    float o[64];
#pragma unroll
    for (int i = 0; i < 64; i++) o[i] = 0.f;
    float mr = -1e30f, l = 0.f;

    __shared__ float4 Ks[64][16];
    __shared__ float4 Vs[64][16];

    for (int m0 = 0; m0 < NN; m0 += 64) {
        __syncthreads();
#pragma unroll
        for (int i = 0; i < 4; i++) {
            int pos = threadIdx.x + i * 256;
            int row = pos >> 4, c4 = pos & 15;
            const float* kr = base + (size_t)(m0 + row) * C3 + 512 + h * HD;
            const float* vr = base + (size_t)(m0 + row) * C3 + 1024 + h * HD;
            Ks[row][c4] = *(const float4*)(kr + c4 * 4);
            Vs[row][c4] = *(const float4*)(vr + c4 * 4);
        }
        __syncthreads();

        for (int j = 0; j < 64; j++) {
            float s0 = 0.f, s1 = 0.f, s2 = 0.f, s3 = 0.f;
#pragma unroll
            for (int c = 0; c < 16; c++) {
                float4 kk = Ks[j][c];
                s0 += q[4 * c]     * kk.x;
                s1 += q[4 * c + 1] * kk.y;
                s2 += q[4 * c + 2] * kk.z;
                s3 += q[4 * c + 3] * kk.w;
            }
            float s = ((s0 + s1) + (s2 + s3)) * 0.125f;
            if (s <= mr) {
                float p = __expf(s - mr);
                l += p;
#pragma unroll
                for (int c = 0; c < 16; c++) {
                    float4 vv = Vs[j][c];
                    o[4 * c]     += p * vv.x;
                    o[4 * c + 1] += p * vv.y;
                    o[4 * c + 2] += p * vv.z;
                    o[4 * c + 3] += p * vv.w;
                }
            } else {
                float r = __expf(mr - s);
                mr = s;
                l = l * r + 1.f;
#pragma unroll
                for (int c = 0; c < 16; c++) {
                    float4 vv = Vs[j][c];
                    o[4 * c]     = o[4 * c]     * r + vv.x;
                    o[4 * c + 1] = o[4 * c + 1] * r + vv.y;
                    o[4 * c + 2] = o[4 * c + 2] * r + vv.z;
                    o[4 * c + 3] = o[4 * c + 3] * r + vv.w;
                }
            }
        }
    }
    float inv = 1.f / l;
    float4* op = (float4*)(HS + (size_t)(bt * NN + n) * 512 + h * HD);
#pragma unroll
    for (int i = 0; i < 16; i++)
        op[i] = make_float4(o[4 * i] * inv, o[4 * i + 1] * inv,
                            o[4 * i + 2] * inv, o[4 * i + 3] * inv);
}

// ---------------- temporal attention (causal over T=24) ----------------
__global__ void __launch_bounds__(192) temporal_attn_k(const float* __restrict__ P,
                                                       float* __restrict__ HT)
{
    const int n = blockIdx.x;
    const int b = blockIdx.y;
    const int h = threadIdx.x & 7;
    const int t = threadIdx.x >> 3;          // 0..23

    float q[64];
    {
        const float4* qp = (const float4*)(P + ((size_t)(b * TT + t) * NN + n) * C3 + 1536 + h * HD);
#pragma unroll
        for (int i = 0; i < 16; i++) {
            float4 v = __ldg(qp + i);
            q[4 * i] = v.x; q[4 * i + 1] = v.y; q[4 * i + 2] = v.z; q[4 * i + 3] = v.w;
        }
    }
    float o[64];
#pragma unroll
    for (int i = 0; i < 64; i++) o[i] = 0.f;
    float mr = -1e30f, l = 0.f;

    for (int s = 0; s <= t; s++) {
        size_t rk = ((size_t)(b * TT + s) * NN + n) * C3;
        const float4* kp = (const float4*)(P + rk + 2048 + h * HD);
        const float4* vp = (const float4*)(P + rk + 2560 + h * HD);
        float s0 = 0.f, s1 = 0.f, s2 = 0.f, s3 = 0.f;
#pragma unroll
        for (int c = 0; c < 16; c++) {
            float4 kk = __ldg(kp + c);
            s0 += q[4 * c]     * kk.x;
            s1 += q[4 * c + 1] * kk.y;
            s2 += q[4 * c + 2] * kk.z;
            s3 += q[4 * c + 3] * kk.w;
        }
        float sc = ((s0 + s1) + (s2 + s3)) * 0.125f;
        if (sc <= mr) {
            float p = __expf(sc - mr);
            l += p;
#pragma unroll
            for (int c = 0; c < 16; c++) {
                float4 vv = __ldg(vp + c);
                o[4 * c]     += p * vv.x;
                o[4 * c + 1] += p * vv.y;
                o[4 * c + 2] += p * vv.z;
                o[4 * c + 3] += p * vv.w;
            }
        } else {
            float r = __expf(mr - sc);
            mr = sc;
            l = l * r + 1.f;
#pragma unroll
            for (int c = 0; c < 16; c++) {
                float4 vv = __ldg(vp + c);
                o[4 * c]     = o[4 * c]     * r + vv.x;
                o[4 * c + 1] = o[4 * c + 1] * r + vv.y;
                o[4 * c + 2] = o[4 * c + 2] * r + vv.z;
                o[4 * c + 3] = o[4 * c + 3] * r + vv.w;
            }
        }
    }
    float inv = 1.f / l;
    float4* op = (float4*)(HT + ((size_t)(b * TT + t) * NN + n) * 512 + h * HD);
#pragma unroll
    for (int i = 0; i < 16; i++)
        op[i] = make_float4(o[4 * i] * inv, o[4 * i + 1] * inv,
                            o[4 * i + 2] * inv, o[4 * i + 3] * inv);
}

// ---------------- gated fusion elementwise ----------------
__global__ void gate_k(const float* __restrict__ Zl, const float* __restrict__ HST,
                       float* __restrict__ H1)
{
    int idx = blockIdx.x * blockDim.x + threadIdx.x;    // float4 units over M*128
    if (idx >= MROWS * 128) return;
    int m = idx >> 7, c4 = idx & 127;
    float4 zl = ((const float4*)Zl)[idx];
    const float4* row = (const float4*)(HST + (size_t)m * 1024);
    float4 hs = row[c4];
    float4 ht = row[128 + c4];
    float zx = 1.f / (1.f + __expf(-zl.x));
    float zy = 1.f / (1.f + __expf(-zl.y));
    float zz = 1.f / (1.f + __expf(-zl.z));
    float zw = 1.f / (1.f + __expf(-zl.w));
    float4 out;
    out.x = zx * hs.x + (1.f - zx) * ht.x;
    out.y = zy * hs.y + (1.f - zy) * ht.y;
    out.z = zz * hs.z + (1.f - zz) * ht.z;
    out.w = zw * hs.w + (1.f - zw) * ht.w;
    ((float4*)H1)[idx] = out;
}

// ---------------- launch ----------------
extern "C" void kernel_launch(void* const* d_in, const int* in_sizes, int n_in,
                              void* d_out, int out_size)
{
    const float* X    = (const float*)d_in[0];
    const float* STE  = (const float*)d_in[1];
    const float* sWq  = (const float*)d_in[2];
    const float* sbq  = (const float*)d_in[3];
    const float* sWk  = (const float*)d_in[4];
    const float* sbk  = (const float*)d_in[5];
    const float* sWv  = (const float*)d_in[6];
    const float* sbv  = (const float*)d_in[7];
    const float* sWo  = (const float*)d_in[8];
    const float* sbo  = (const float*)d_in[9];
    const float* tWq  = (const float*)d_in[10];
    const float* tbq  = (const float*)d_in[11];
    const float* tWk  = (const float*)d_in[12];
    const float* tbk  = (const float*)d_in[13];
    const float* tWv  = (const float*)d_in[14];
    const float* tbv  = (const float*)d_in[15];
    const float* tWo  = (const float*)d_in[16];
    const float* tbo  = (const float*)d_in[17];
    const float* gWxs = (const float*)d_in[18];
    const float* gWxt = (const float*)d_in[19];
    const float* gbxt = (const float*)d_in[20];
    const float* gWh1 = (const float*)d_in[21];
    const float* gbh1 = (const float*)d_in[22];
    const float* gWh2 = (const float*)d_in[23];
    const float* gbh2 = (const float*)d_in[24];
    float* out = (float*)d_out;

    float *Xc, *P, *Wcat, *bcat, *Wg, *HS, *HT, *HST;
    cudaGetSymbolAddress((void**)&Xc,   g_Xc);
    cudaGetSymbolAddress((void**)&P,    g_P);
    cudaGetSymbolAddress((void**)&Wcat, g_Wcat);
    cudaGetSymbolAddress((void**)&bcat, g_bcat);
    cudaGetSymbolAddress((void**)&Wg,   g_Wg);
    cudaGetSymbolAddress((void**)&HS,   g_HS);
    cudaGetSymbolAddress((void**)&HT,   g_HT);
    cudaGetSymbolAddress((void**)&HST,  g_HST);

    // 1) build Xc = [X | STE]  and concatenated weights
    concat_xc_k<<<(MROWS * 384 + 255) / 256, 256>>>(X, STE, Xc);
    concat_w_k<<<(1536 * 3072 + 255) / 256, 256>>>(sWq, sWk, sWv, tWq, tWk, tWv,
                                                   sbq, sbk, sbv, tbq, tbk, tbv,
                                                   Wcat, bcat);
    concat_wg_k<<<(1024 * 512 + 255) / 256, 256>>>(gWxs, gWxt, Wg);

    // 2) all six projections in one GEMM (relu epilogue): P = relu(Xc @ Wcat + bcat)
    gemm_tf32_k<1><<<dim3(24, 192), 256>>>(Xc, Wcat, bcat, nullptr, P,
                                           MROWS, 3072, 1536, 1536, 3072, 3072);

    // 3) attention
    spatial_attn_k<<<BB * TT * NH * 2, 256>>>(P, HS);
    temporal_attn_k<<<dim3(NN, BB), 192>>>(P, HT);

    // 4) output projections into HST = [relu(HS@sWo+b) | relu(HT@tWo+b)]
    gemm_tf32_k<1><<<dim3(4, 192), 256>>>(HS, sWo, sbo, nullptr, HST,
                                          MROWS, 512, 512, 512, 512, 1024);
    gemm_tf32_k<1><<<dim3(4, 192), 256>>>(HT, tWo, tbo, nullptr, HST + 512,
                                          MROWS, 512, 512, 512, 512, 1024);

    // 5) gate: Zlin = HST @ [gWxs; gWxt] + gbxt  (into HS buffer)
    gemm_tf32_k<0><<<dim3(4, 192), 256>>>(HST, Wg, gbxt, nullptr, HS,
                                          MROWS, 512, 1024, 1024, 512, 512);
    // H1 = sigmoid(Zlin)*HSp + (1-sigmoid)*HTp   (into HT buffer)
    gate_k<<<(MROWS * 128 + 255) / 256, 256>>>(HS, HST, HT);

    // 6) MLP: H2 = relu(H1 @ gWh1 + gbh1)  (into HS buffer)
    gemm_tf32_k<1><<<dim3(4, 192), 256>>>(HT, gWh1, gbh1, nullptr, HS,
                                          MROWS, 512, 512, 512, 512, 512);
    // out = X + H2 @ gWh2 + gbh2
    gemm_tf32_k<2><<<dim3(4, 192), 256>>>(HS, gWh2, gbh2, X, out,
                                          MROWS, 512, 512, 512, 512, 512);
}

// round 4
// speedup vs baseline: 1.2917x; 1.0040x over previous
#include <cuda_runtime.h>
#include <mma.h>
using namespace nvcuda;

// ---------------- problem constants ----------------
#define BB 2
#define TT 24
#define NN 512
#define DD 512
#define NH 8
#define HD 64
#define MROWS (BB*TT*NN)      // 24576
#define C3 3072               // P row stride: [sQ sK sV tQ tK tV]

// ---------------- scratch (static device globals; no allocation) ----------------
__device__ float g_Xc [(size_t)MROWS * 1536];   // concat(X, STE)
__device__ float g_P  [(size_t)MROWS * 3072];   // all six projections, relu'd
__device__ float g_Wcat[1536 * 3072];
__device__ float g_bcat[3072];
__device__ float g_Wg  [1024 * 512];
__device__ float g_HS [(size_t)MROWS * 512];
__device__ float g_HT [(size_t)MROWS * 512];
__device__ float g_HST[(size_t)MROWS * 1024];

// ---------------- concat kernels ----------------
__global__ void concat_xc_k(const float* __restrict__ X, const float* __restrict__ STE,
                            float* __restrict__ Xc)
{
    int idx = blockIdx.x * blockDim.x + threadIdx.x;   // float4 units
    if (idx >= MROWS * 384) return;
    int m = idx / 384, c4 = idx % 384;
    float4 v;
    if (c4 < 128) v = ((const float4*)X)[(size_t)m * 128 + c4];
    else          v = ((const float4*)STE)[(size_t)m * 256 + (c4 - 128)];
    ((float4*)Xc)[idx] = v;
}

__global__ void concat_w_k(const float* __restrict__ w0, const float* __restrict__ w1,
                           const float* __restrict__ w2, const float* __restrict__ w3,
                           const float* __restrict__ w4, const float* __restrict__ w5,
                           const float* __restrict__ b0, const float* __restrict__ b1,
                           const float* __restrict__ b2, const float* __restrict__ b3,
                           const float* __restrict__ b4, const float* __restrict__ b5,
                           float* __restrict__ Wc, float* __restrict__ bc)
{
    int idx = blockIdx.x * blockDim.x + threadIdx.x;
    if (idx < 1536 * 3072) {
        int k = idx / 3072, n = idx % 3072;
        int j = n >> 9, c = n & 511;
        const float* ws[6] = {w0, w1, w2, w3, w4, w5};
        Wc[idx] = ws[j][k * 512 + c];
    }
    if (idx < 3072) {
        int j = idx >> 9, c = idx & 511;
        const float* bs[6] = {b0, b1, b2, b3, b4, b5};
        bc[idx] = bs[j][c];
    }
}

__global__ void concat_wg_k(const float* __restrict__ wxs, const float* __restrict__ wxt,
                            float* __restrict__ Wg)
{
    int idx = blockIdx.x * blockDim.x + threadIdx.x;
    if (idx >= 1024 * 512) return;
    int k = idx / 512, c = idx % 512;
    Wg[idx] = (k < 512) ? wxs[k * 512 + c] : wxt[(k - 512) * 512 + c];
}

// ---------------- tf32 tensor-core GEMM 128x128, BK=16 double-buffered ----------------
// ACT: 0 = bias only, 1 = bias + relu, 2 = bias + residual add,
//      3 = gated fusion: out = sig(acc+bias)*R[col] + (1-sig)*R[512+col]
// Requires: M%128==0, N%128==0, K%16==0.
#define A_LD 24
#define B_LD 136
#define AS_STRIDE (128 * A_LD)   // 3072 floats per buffer
#define BS_STRIDE (16 * B_LD)    // 2176 floats per buffer

__device__ __forceinline__ float4 tf32_4(float4 v) {
    v.x = wmma::__float_to_tf32(v.x);
    v.y = wmma::__float_to_tf32(v.y);
    v.z = wmma::__float_to_tf32(v.z);
    v.w = wmma::__float_to_tf32(v.w);
    return v;
}

template<int ACT>
__global__ void __launch_bounds__(256, 2) gemm_tf32_k(
    const float* __restrict__ A, const float* __restrict__ B,
    const float* __restrict__ bias, const float* __restrict__ R,
    float* __restrict__ C, int M, int N, int K, int lda, int ldb, int ldc, int ldr)
{
    __shared__ float smem[2 * AS_STRIDE + 2 * BS_STRIDE];   // 41984 B
    float* As = smem;
    float* Bs = smem + 2 * AS_STRIDE;

    const int tid  = threadIdx.x;
    const int warp = tid >> 5;
    const int lane = tid & 31;
    const int wm   = warp & 3;    // M subtile (32 rows each)
    const int wn   = warp >> 2;   // N subtile (64 cols each)
    const int m0 = blockIdx.y * 128;
    const int n0 = blockIdx.x * 128;

    // global->smem load mapping
    const int a_row = tid >> 2;          // 0..63 (two passes cover 128 rows)
    const int a_c4  = (tid & 3) << 2;    // 0,4,8,12
    const int b_row = tid >> 5;          // 0..7 (two passes cover 16 rows)
    const int b_c4  = (tid & 31) << 2;   // 0..124

    wmma::fragment<wmma::accumulator, 16, 16, 8, float> acc[2][4];
#pragma unroll
    for (int i = 0; i < 2; i++)
#pragma unroll
        for (int j = 0; j < 4; j++) wmma::fill_fragment(acc[i][j], 0.f);

    // preload tile 0 (convert to tf32 at store — no cvt in the mma loop)
    {
        float4 va0 = tf32_4(*(const float4*)(A + (size_t)(m0 + a_row) * lda + a_c4));
        float4 va1 = tf32_4(*(const float4*)(A + (size_t)(m0 + 64 + a_row) * lda + a_c4));
        float4 vb0 = tf32_4(*(const float4*)(B + (size_t)b_row * ldb + n0 + b_c4));
        float4 vb1 = tf32_4(*(const float4*)(B + (size_t)(8 + b_row) * ldb + n0 + b_c4));
        *(float4*)(As + a_row * A_LD + a_c4)        = va0;
        *(float4*)(As + (64 + a_row) * A_LD + a_c4) = va1;
        *(float4*)(Bs + b_row * B_LD + b_c4)        = vb0;
        *(float4*)(Bs + (8 + b_row) * B_LD + b_c4)  = vb1;
    }
    __syncthreads();

    const int nk = K >> 4;
    for (int kt = 0; kt < nk; kt++) {
        const int buf = kt & 1;
        float4 pa0, pa1, pb0, pb1;
        const bool pref = (kt + 1 < nk);
        if (pref) {
            int k0 = (kt + 1) << 4;
            pa0 = *(const float4*)(A + (size_t)(m0 + a_row) * lda + k0 + a_c4);
            pa1 = *(const float4*)(A + (size_t)(m0 + 64 + a_row) * lda + k0 + a_c4);
            pb0 = *(const float4*)(B + (size_t)(k0 + b_row) * ldb + n0 + b_c4);
            pb1 = *(const float4*)(B + (size_t)(k0 + 8 + b_row) * ldb + n0 + b_c4);
        }

        const float* Ab = As + buf * AS_STRIDE;
        const float* Bb = Bs + buf * BS_STRIDE;
#pragma unroll
        for (int ks = 0; ks < 2; ks++) {
            wmma::fragment<wmma::matrix_a, 16, 16, 8, wmma::precision::tf32, wmma::row_major> af[2];
            wmma::fragment<wmma::matrix_b, 16, 16, 8, wmma::precision::tf32, wmma::row_major> bf[4];
#pragma unroll
            for (int fm = 0; fm < 2; fm++)
                wmma::load_matrix_sync(af[fm], Ab + (wm * 32 + fm * 16) * A_LD + ks * 8, A_LD);
#pragma unroll
            for (int fn = 0; fn < 4; fn++)
                wmma::load_matrix_sync(bf[fn], Bb + (ks * 8) * B_LD + wn * 64 + fn * 16, B_LD);
#pragma unroll
            for (int fm = 0; fm < 2; fm++)
#pragma unroll
                for (int fn = 0; fn < 4; fn++)
                    wmma::mma_sync(acc[fm][fn], af[fm], bf[fn], acc[fm][fn]);
        }

        if (pref) {
            float* An = As + (buf ^ 1) * AS_STRIDE;
            float* Bn = Bs + (buf ^ 1) * BS_STRIDE;
            *(float4*)(An + a_row * A_LD + a_c4)        = tf32_4(pa0);
            *(float4*)(An + (64 + a_row) * A_LD + a_c4) = tf32_4(pa1);
            *(float4*)(Bn + b_row * B_LD + b_c4)        = tf32_4(pb0);
            *(float4*)(Bn + (8 + b_row) * B_LD + b_c4)  = tf32_4(pb1);
        }
        __syncthreads();
    }

    // epilogue: per-warp smem scratch (32 rows x 40 stride), two 32-col halves
    float* sw = smem + warp * (32 * 40);
#pragma unroll
    for (int h = 0; h < 2; h++) {
#pragma unroll
        for (int fm = 0; fm < 2; fm++)
#pragma unroll
            for (int fnl = 0; fnl < 2; fnl++)
                wmma::store_matrix_sync(sw + fm * 16 * 40 + fnl * 16,
                                        acc[fm][h * 2 + fnl], 40, wmma::mem_row_major);
        __syncwarp();
        const int colbase = n0 + wn * 64 + h * 32;
#pragma unroll
        for (int i = 0; i < 8; i++) {
            int idx = lane + i * 32;        // 0..255
            int r  = idx >> 3;              // 0..31
            int c4 = (idx & 7) << 2;        // 0..28
            float4 v = *(float4*)(sw + r * 40 + c4);
            int row = m0 + wm * 32 + r;
            int col = colbase + c4;
            float4 bv = *(const float4*)(bias + col);
            v.x += bv.x; v.y += bv.y; v.z += bv.z; v.w += bv.w;
            if (ACT == 1) {
                v.x = fmaxf(v.x, 0.f); v.y = fmaxf(v.y, 0.f);
                v.z = fmaxf(v.z, 0.f); v.w = fmaxf(v.w, 0.f);
            }
            if (ACT == 2) {
                float4 rv = *(const float4*)(R + (size_t)row * ldr + col);
                v.x += rv.x; v.y += rv.y; v.z += rv.z; v.w += rv.w;
            }
            if (ACT == 3) {
                float4 hs = *(const float4*)(R + (size_t)row * ldr + col);
                float4 ht = *(const float4*)(R + (size_t)row * ldr + 512 + col);
                float zx = 1.f / (1.f + __expf(-v.x));
                float zy = 1.f / (1.f + __expf(-v.y));
                float zz = 1.f / (1.f + __expf(-v.z));
                float zw = 1.f / (1.f + __expf(-v.w));
                v.x = zx * hs.x + (1.f - zx) * ht.x;
                v.y = zy * hs.y + (1.f - zy) * ht.y;
                v.z = zz * hs.z + (1.f - zz) * ht.z;
                v.w = zw * hs.w + (1.f - zw) * ht.w;
            }
            *(float4*)(C + (size_t)row * ldc + col) = v;
        }
        __syncwarp();
    }
}

// ---------------- spatial attention: flash-style, 1 query row per thread ----------------
__global__ void __launch_bounds__(256) spatial_attn_k(const float* __restrict__ P,
                                                      float* __restrict__ HS)
{
    const int bid  = blockIdx.x;
    const int half = bid & 1;
    const int h    = (bid >> 1) & 7;
    const int bt   = bid >> 4;               // 0..47
    const int n    = half * 256 + threadIdx.x;
    const float* base = P + (size_t)bt * NN * C3;

    float q[64];
    {
        const float4* qp = (const float4*)(base + (size_t)n * C3 + h * HD);
#pragma unroll
        for (int i = 0; i < 16; i++) {
            float4 v = qp[i];
            q[4 * i] = v.x; q[4 * i + 1] = v.y; q[4 * i + 2] = v.z; q[4 * i + 3] = v.w;
        }
    }
    float o[64];
#pragma unroll
    for (int i = 0; i < 64; i++) o[i] = 0.f;
    float mr = -1e30f, l = 0.f;

    __shared__ float4 Ks[64][16];
    __shared__ float4 Vs[64][16];

    for (int m0 = 0; m0 < NN; m0 += 64) {
        __syncthreads();
#pragma unroll
        for (int i = 0; i < 4; i++) {
            int pos = threadIdx.x + i * 256;
            int row = pos >> 4, c4 = pos & 15;
            const float* kr = base + (size_t)(m0 + row) * C3 + 512 + h * HD;
            const float* vr = base + (size_t)(m0 + row) * C3 + 1024 + h * HD;
            Ks[row][c4] = *(const float4*)(kr + c4 * 4);
            Vs[row][c4] = *(const float4*)(vr + c4 * 4);
        }
        __syncthreads();

        for (int j = 0; j < 64; j++) {
            float s0 = 0.f, s1 = 0.f, s2 = 0.f, s3 = 0.f;
#pragma unroll
            for (int c = 0; c < 16; c++) {
                float4 kk = Ks[j][c];
                s0 += q[4 * c]     * kk.x;
                s1 += q[4 * c + 1] * kk.y;
                s2 += q[4 * c + 2] * kk.z;
                s3 += q[4 * c + 3] * kk.w;
            }
            float s = ((s0 + s1) + (s2 + s3)) * 0.125f;
            if (s <= mr) {
                float p = __expf(s - mr);
                l += p;
#pragma unroll
                for (int c = 0; c < 16; c++) {
                    float4 vv = Vs[j][c];
                    o[4 * c]     += p * vv.x;
                    o[4 * c + 1] += p * vv.y;
                    o[4 * c + 2] += p * vv.z;
                    o[4 * c + 3] += p * vv.w;
                }
            } else {
                float r = __expf(mr - s);
                mr = s;
                l = l * r + 1.f;
#pragma unroll
                for (int c = 0; c < 16; c++) {
                    float4 vv = Vs[j][c];
                    o[4 * c]     = o[4 * c]     * r + vv.x;
                    o[4 * c + 1] = o[4 * c + 1] * r + vv.y;
                    o[4 * c + 2] = o[4 * c + 2] * r + vv.z;
                    o[4 * c + 3] = o[4 * c + 3] * r + vv.w;
                }
            }
        }
    }
    float inv = 1.f / l;
    float4* op = (float4*)(HS + (size_t)(bt * NN + n) * 512 + h * HD);
#pragma unroll
    for (int i = 0; i < 16; i++)
        op[i] = make_float4(o[4 * i] * inv, o[4 * i + 1] * inv,
                            o[4 * i + 2] * inv, o[4 * i + 3] * inv);
}

// ---------------- temporal attention (causal over T=24) ----------------
__global__ void __launch_bounds__(192) temporal_attn_k(const float* __restrict__ P,
                                                       float* __restrict__ HT)
{
    const int n = blockIdx.x;
    const int b = blockIdx.y;
    const int h = threadIdx.x & 7;
    const int t = threadIdx.x >> 3;          // 0..23

    float q[64];
    {
        const float4* qp = (const float4*)(P + ((size_t)(b * TT + t) * NN + n) * C3 + 1536 + h * HD);
#pragma unroll
        for (int i = 0; i < 16; i++) {
            float4 v = __ldg(qp + i);
            q[4 * i] = v.x; q[4 * i + 1] = v.y; q[4 * i + 2] = v.z; q[4 * i + 3] = v.w;
        }
    }
    float o[64];
#pragma unroll
    for (int i = 0; i < 64; i++) o[i] = 0.f;
    float mr = -1e30f, l = 0.f;

    for (int s = 0; s <= t; s++) {
        size_t rk = ((size_t)(b * TT + s) * NN + n) * C3;
        const float4* kp = (const float4*)(P + rk + 2048 + h * HD);
        const float4* vp = (const float4*)(P + rk + 2560 + h * HD);
        float s0 = 0.f, s1 = 0.f, s2 = 0.f, s3 = 0.f;
#pragma unroll
        for (int c = 0; c < 16; c++) {
            float4 kk = __ldg(kp + c);
            s0 += q[4 * c]     * kk.x;
            s1 += q[4 * c + 1] * kk.y;
            s2 += q[4 * c + 2] * kk.z;
            s3 += q[4 * c + 3] * kk.w;
        }
        float sc = ((s0 + s1) + (s2 + s3)) * 0.125f;
        if (sc <= mr) {
            float p = __expf(sc - mr);
            l += p;
#pragma unroll
            for (int c = 0; c < 16; c++) {
                float4 vv = __ldg(vp + c);
                o[4 * c]     += p * vv.x;
                o[4 * c + 1] += p * vv.y;
                o[4 * c + 2] += p * vv.z;
                o[4 * c + 3] += p * vv.w;
            }
        } else {
            float r = __expf(mr - sc);
            mr = sc;
            l = l * r + 1.f;
#pragma unroll
            for (int c = 0; c < 16; c++) {
                float4 vv = __ldg(vp + c);
                o[4 * c]     = o[4 * c]     * r + vv.x;
                o[4 * c + 1] = o[4 * c + 1] * r + vv.y;
                o[4 * c + 2] = o[4 * c + 2] * r + vv.z;
                o[4 * c + 3] = o[4 * c + 3] * r + vv.w;
            }
        }
    }
    float inv = 1.f / l;
    float4* op = (float4*)(HT + ((size_t)(b * TT + t) * NN + n) * 512 + h * HD);
#pragma unroll
    for (int i = 0; i < 16; i++)
        op[i] = make_float4(o[4 * i] * inv, o[4 * i + 1] * inv,
                            o[4 * i + 2] * inv, o[4 * i + 3] * inv);
}

// ---------------- launch ----------------
extern "C" void kernel_launch(void* const* d_in, const int* in_sizes, int n_in,
                              void* d_out, int out_size)
{
    const float* X    = (const float*)d_in[0];
    const float* STE  = (const float*)d_in[1];
    const float* sWq  = (const float*)d_in[2];
    const float* sbq  = (const float*)d_in[3];
    const float* sWk  = (const float*)d_in[4];
    const float* sbk  = (const float*)d_in[5];
    const float* sWv  = (const float*)d_in[6];
    const float* sbv  = (const float*)d_in[7];
    const float* sWo  = (const float*)d_in[8];
    const float* sbo  = (const float*)d_in[9];
    const float* tWq  = (const float*)d_in[10];
    const float* tbq  = (const float*)d_in[11];
    const float* tWk  = (const float*)d_in[12];
    const float* tbk  = (const float*)d_in[13];
    const float* tWv  = (const float*)d_in[14];
    const float* tbv  = (const float*)d_in[15];
    const float* tWo  = (const float*)d_in[16];
    const float* tbo  = (const float*)d_in[17];
    const float* gWxs = (const float*)d_in[18];
    const float* gWxt = (const float*)d_in[19];
    const float* gbxt = (const float*)d_in[20];
    const float* gWh1 = (const float*)d_in[21];
    const float* gbh1 = (const float*)d_in[22];
    const float* gWh2 = (const float*)d_in[23];
    const float* gbh2 = (const float*)d_in[24];
    float* out = (float*)d_out;

    float *Xc, *P, *Wcat, *bcat, *Wg, *HS, *HT, *HST;
    cudaGetSymbolAddress((void**)&Xc,   g_Xc);
    cudaGetSymbolAddress((void**)&P,    g_P);
    cudaGetSymbolAddress((void**)&Wcat, g_Wcat);
    cudaGetSymbolAddress((void**)&bcat, g_bcat);
    cudaGetSymbolAddress((void**)&Wg,   g_Wg);
    cudaGetSymbolAddress((void**)&HS,   g_HS);
    cudaGetSymbolAddress((void**)&HT,   g_HT);
    cudaGetSymbolAddress((void**)&HST,  g_HST);

    // 1) build Xc = [X | STE]  and concatenated weights
    concat_xc_k<<<(MROWS * 384 + 255) / 256, 256>>>(X, STE, Xc);
    concat_w_k<<<(1536 * 3072 + 255) / 256, 256>>>(sWq, sWk, sWv, tWq, tWk, tWv,
                                                   sbq, sbk, sbv, tbq, tbk, tbv,
                                                   Wcat, bcat);
    concat_wg_k<<<(1024 * 512 + 255) / 256, 256>>>(gWxs, gWxt, Wg);

    // 2) all six projections in one GEMM (relu epilogue): P = relu(Xc @ Wcat + bcat)
    gemm_tf32_k<1><<<dim3(24, 192), 256>>>(Xc, Wcat, bcat, nullptr, P,
                                           MROWS, 3072, 1536, 1536, 3072, 3072, 0);

    // 3) attention
    spatial_attn_k<<<BB * TT * NH * 2, 256>>>(P, HS);
    temporal_attn_k<<<dim3(NN, BB), 192>>>(P, HT);

    // 4) output projections into HST = [relu(HS@sWo+b) | relu(HT@tWo+b)]
    gemm_tf32_k<1><<<dim3(4, 192), 256>>>(HS, sWo, sbo, nullptr, HST,
                                          MROWS, 512, 512, 512, 512, 1024, 0);
    gemm_tf32_k<1><<<dim3(4, 192), 256>>>(HT, tWo, tbo, nullptr, HST + 512,
                                          MROWS, 512, 512, 512, 512, 1024, 0);

    // 5) gated fusion fully inside the GEMM epilogue:
    //    H1 = sig(HST@Wg + gbxt) * HSp + (1-sig) * HTp   (into HT buffer)
    gemm_tf32_k<3><<<dim3(4, 192), 256>>>(HST, Wg, gbxt, HST, HT,
                                          MROWS, 512, 1024, 1024, 512, 512, 1024);

    // 6) MLP: H2 = relu(H1 @ gWh1 + gbh1)  (into HS buffer)
    gemm_tf32_k<1><<<dim3(4, 192), 256>>>(HT, gWh1, gbh1, nullptr, HS,
                                          MROWS, 512, 512, 512, 512, 512, 0);
    // out = X + H2 @ gWh2 + gbh2
    gemm_tf32_k<2><<<dim3(4, 192), 256>>>(HS, gWh2, gbh2, X, out,
                                          MROWS, 512, 512, 512, 512, 512, 512);
}

// round 5
// speedup vs baseline: 2.6076x; 2.0187x over previous
#include <cuda_runtime.h>
#include <cuda_fp16.h>
#include <mma.h>
using namespace nvcuda;

// ---------------- problem constants ----------------
#define BB 2
#define TT 24
#define NN 512
#define DD 512
#define NH 8
#define HD 64
#define MROWS (BB*TT*NN)      // 24576
#define C3 3072               // P row stride: [sQ sK sV tQ tK tV]

// ---------------- scratch (static device globals; no allocation) ----------------
__device__ float g_P  [(size_t)MROWS * 3072];   // all six projections, relu'd
__device__ float g_Wcat[1536 * 3072];
__device__ float g_bcat[3072];
__device__ float g_Wg  [1024 * 512];
__device__ float g_HS [(size_t)MROWS * 512];
__device__ float g_HT [(size_t)MROWS * 512];
__device__ float g_HST[(size_t)MROWS * 1024];

// ---------------- weight concat kernels ----------------
__global__ void concat_w_k(const float* __restrict__ w0, const float* __restrict__ w1,
                           const float* __restrict__ w2, const float* __restrict__ w3,
                           const float* __restrict__ w4, const float* __restrict__ w5,
                           const float* __restrict__ b0, const float* __restrict__ b1,
                           const float* __restrict__ b2, const float* __restrict__ b3,
                           const float* __restrict__ b4, const float* __restrict__ b5,
                           float* __restrict__ Wc, float* __restrict__ bc)
{
    int idx = blockIdx.x * blockDim.x + threadIdx.x;
    if (idx < 1536 * 3072) {
        int k = idx / 3072, n = idx % 3072;
        int j = n >> 9, c = n & 511;
        const float* ws[6] = {w0, w1, w2, w3, w4, w5};
        Wc[idx] = ws[j][k * 512 + c];
    }
    if (idx < 3072) {
        int j = idx >> 9, c = idx & 511;
        const float* bs[6] = {b0, b1, b2, b3, b4, b5};
        bc[idx] = bs[j][c];
    }
}

__global__ void concat_wg_k(const float* __restrict__ wxs, const float* __restrict__ wxt,
                            float* __restrict__ Wg)
{
    int idx = blockIdx.x * blockDim.x + threadIdx.x;
    if (idx >= 1024 * 512) return;
    int k = idx / 512, c = idx % 512;
    Wg[idx] = (k < 512) ? wxs[k * 512 + c] : wxt[(k - 512) * 512 + c];
}

// ---------------- fp16 tensor-core GEMM 128x128, BK=16 double-buffered ----------------
// ACT: 0 bias, 1 bias+relu, 2 bias+residual, 3 gated fusion
// AMODE: 0 = plain A[lda], 1 = A is concat(X[512] | STE[1024]) per row
#define A_LDH 24
#define B_LDH 136
#define AS_STRIDE (128 * A_LDH)   // halves per buffer (6144B)
#define BS_STRIDE (16 * B_LDH)    // halves per buffer (4352B)
#define SMEM_BYTES 41984

__device__ __forceinline__ uint2 f4_to_h4(float4 v) {
    __half2 a = __floats2half2_rn(v.x, v.y);
    __half2 b = __floats2half2_rn(v.z, v.w);
    uint2 r;
    r.x = *(unsigned*)&a;
    r.y = *(unsigned*)&b;
    return r;
}

template<int AMODE>
__device__ __forceinline__ float4 ldA(const float* __restrict__ A,
                                      const float* __restrict__ A2,
                                      int m, int c, int lda)
{
    if (AMODE == 1) {
        if (c < 512) return *(const float4*)(A  + (size_t)m * 512  + c);
        else         return *(const float4*)(A2 + (size_t)m * 1024 + (c - 512));
    }
    return *(const float4*)(A + (size_t)m * lda + c);
}

template<int ACT, int AMODE>
__global__ void __launch_bounds__(256, 2) gemm_h_k(
    const float* __restrict__ A, const float* __restrict__ A2,
    const float* __restrict__ B,
    const float* __restrict__ bias, const float* __restrict__ R,
    float* __restrict__ C, int M, int N, int K, int lda, int ldb, int ldc, int ldr)
{
    __shared__ __align__(16) char smem_raw[SMEM_BYTES];
    __half* As = (__half*)smem_raw;
    __half* Bs = (__half*)smem_raw + 2 * AS_STRIDE;

    const int tid  = threadIdx.x;
    const int warp = tid >> 5;
    const int lane = tid & 31;
    const int wm   = warp & 3;    // 32-row subtile
    const int wn   = warp >> 2;   // 64-col subtile
    const int m0 = blockIdx.y * 128;
    const int n0 = blockIdx.x * 128;

    const int a_row = tid >> 2;          // 0..63 (two passes)
    const int a_c4  = (tid & 3) << 2;    // 0,4,8,12
    const int b_row = tid >> 5;          // 0..7 (two passes)
    const int b_c4  = (tid & 31) << 2;   // 0..124

    wmma::fragment<wmma::accumulator, 16, 16, 16, float> acc[2][4];
#pragma unroll
    for (int i = 0; i < 2; i++)
#pragma unroll
        for (int j = 0; j < 4; j++) wmma::fill_fragment(acc[i][j], 0.f);

    // preload tile 0
    {
        float4 va0 = ldA<AMODE>(A, A2, m0 + a_row,      a_c4, lda);
        float4 va1 = ldA<AMODE>(A, A2, m0 + 64 + a_row, a_c4, lda);
        float4 vb0 = *(const float4*)(B + (size_t)b_row * ldb + n0 + b_c4);
        float4 vb1 = *(const float4*)(B + (size_t)(8 + b_row) * ldb + n0 + b_c4);
        *(uint2*)(As + a_row * A_LDH + a_c4)        = f4_to_h4(va0);
        *(uint2*)(As + (64 + a_row) * A_LDH + a_c4) = f4_to_h4(va1);
        *(uint2*)(Bs + b_row * B_LDH + b_c4)        = f4_to_h4(vb0);
        *(uint2*)(Bs + (8 + b_row) * B_LDH + b_c4)  = f4_to_h4(vb1);
    }
    __syncthreads();

    const int nk = K >> 4;
    for (int kt = 0; kt < nk; kt++) {
        const int buf = kt & 1;
        float4 pa0, pa1, pb0, pb1;
        const bool pref = (kt + 1 < nk);
        if (pref) {
            int k0 = (kt + 1) << 4;
            pa0 = ldA<AMODE>(A, A2, m0 + a_row,      k0 + a_c4, lda);
            pa1 = ldA<AMODE>(A, A2, m0 + 64 + a_row, k0 + a_c4, lda);
            pb0 = *(const float4*)(B + (size_t)(k0 + b_row) * ldb + n0 + b_c4);
            pb1 = *(const float4*)(B + (size_t)(k0 + 8 + b_row) * ldb + n0 + b_c4);
        }

        const __half* Ab = As + buf * AS_STRIDE;
        const __half* Bb = Bs + buf * BS_STRIDE;

        wmma::fragment<wmma::matrix_a, 16, 16, 16, __half, wmma::row_major> af[2];
#pragma unroll
        for (int fm = 0; fm < 2; fm++)
            wmma::load_matrix_sync(af[fm], Ab + (wm * 32 + fm * 16) * A_LDH, A_LDH);
#pragma unroll
        for (int fn = 0; fn < 4; fn++) {
            wmma::fragment<wmma::matrix_b, 16, 16, 16, __half, wmma::row_major> bf;
            wmma::load_matrix_sync(bf, Bb + wn * 64 + fn * 16, B_LDH);
#pragma unroll
            for (int fm = 0; fm < 2; fm++)
                wmma::mma_sync(acc[fm][fn], af[fm], bf, acc[fm][fn]);
        }

        if (pref) {
            __half* An = As + (buf ^ 1) * AS_STRIDE;
            __half* Bn = Bs + (buf ^ 1) * BS_STRIDE;
            *(uint2*)(An + a_row * A_LDH + a_c4)        = f4_to_h4(pa0);
            *(uint2*)(An + (64 + a_row) * A_LDH + a_c4) = f4_to_h4(pa1);
            *(uint2*)(Bn + b_row * B_LDH + b_c4)        = f4_to_h4(pb0);
            *(uint2*)(Bn + (8 + b_row) * B_LDH + b_c4)  = f4_to_h4(pb1);
        }
        __syncthreads();
    }

    // epilogue: per-warp fp32 scratch (32 rows x 40 stride)
    float* sw = (float*)smem_raw + warp * (32 * 40);
#pragma unroll
    for (int h = 0; h < 2; h++) {
#pragma unroll
        for (int fm = 0; fm < 2; fm++)
#pragma unroll
            for (int fnl = 0; fnl < 2; fnl++)
                wmma::store_matrix_sync(sw + fm * 16 * 40 + fnl * 16,
                                        acc[fm][h * 2 + fnl], 40, wmma::mem_row_major);
        __syncwarp();
        const int colbase = n0 + wn * 64 + h * 32;
#pragma unroll
        for (int i = 0; i < 8; i++) {
            int idx = lane + i * 32;
            int r  = idx >> 3;
            int c4 = (idx & 7) << 2;
            float4 v = *(float4*)(sw + r * 40 + c4);
            int row = m0 + wm * 32 + r;
            int col = colbase + c4;
            float4 bv = *(const float4*)(bias + col);
            v.x += bv.x; v.y += bv.y; v.z += bv.z; v.w += bv.w;
            if (ACT == 1) {
                v.x = fmaxf(v.x, 0.f); v.y = fmaxf(v.y, 0.f);
                v.z = fmaxf(v.z, 0.f); v.w = fmaxf(v.w, 0.f);
            }
            if (ACT == 2) {
                float4 rv = *(const float4*)(R + (size_t)row * ldr + col);
                v.x += rv.x; v.y += rv.y; v.z += rv.z; v.w += rv.w;
            }
            if (ACT == 3) {
                float4 hs = *(const float4*)(R + (size_t)row * ldr + col);
                float4 ht = *(const float4*)(R + (size_t)row * ldr + 512 + col);
                float zx = 1.f / (1.f + __expf(-v.x));
                float zy = 1.f / (1.f + __expf(-v.y));
                float zz = 1.f / (1.f + __expf(-v.z));
                float zw = 1.f / (1.f + __expf(-v.w));
                v.x = zx * hs.x + (1.f - zx) * ht.x;
                v.y = zy * hs.y + (1.f - zy) * ht.y;
                v.z = zz * hs.z + (1.f - zz) * ht.z;
                v.w = zw * hs.w + (1.f - zw) * ht.w;
            }
            *(float4*)(C + (size_t)row * ldc + col) = v;
        }
        __syncwarp();
    }
}

// ---------------- spatial attention: flash-style, 1 query row per thread ----------------
__global__ void __launch_bounds__(256) spatial_attn_k(const float* __restrict__ P,
                                                      float* __restrict__ HS)
{
    const int bid  = blockIdx.x;
    const int half = bid & 1;
    const int h    = (bid >> 1) & 7;
    const int bt   = bid >> 4;               // 0..47
    const int n    = half * 256 + threadIdx.x;
    const float* base = P + (size_t)bt * NN * C3;

    float q[64];
    {
        const float4* qp = (const float4*)(base + (size_t)n * C3 + h * HD);
#pragma unroll
        for (int i = 0; i < 16; i++) {
            float4 v = qp[i];
            q[4 * i] = v.x; q[4 * i + 1] = v.y; q[4 * i + 2] = v.z; q[4 * i + 3] = v.w;
        }
    }
    float o[64];
#pragma unroll
    for (int i = 0; i < 64; i++) o[i] = 0.f;
    float mr = -1e30f, l = 0.f;

    __shared__ float4 Ks[64][16];
    __shared__ float4 Vs[64][16];

    for (int m0 = 0; m0 < NN; m0 += 64) {
        __syncthreads();
#pragma unroll
        for (int i = 0; i < 4; i++) {
            int pos = threadIdx.x + i * 256;
            int row = pos >> 4, c4 = pos & 15;
            const float* kr = base + (size_t)(m0 + row) * C3 + 512 + h * HD;
            const float* vr = base + (size_t)(m0 + row) * C3 + 1024 + h * HD;
            Ks[row][c4] = *(const float4*)(kr + c4 * 4);
            Vs[row][c4] = *(const float4*)(vr + c4 * 4);
        }
        __syncthreads();

        for (int j = 0; j < 64; j++) {
            float s0 = 0.f, s1 = 0.f, s2 = 0.f, s3 = 0.f;
#pragma unroll
            for (int c = 0; c < 16; c++) {
                float4 kk = Ks[j][c];
                s0 += q[4 * c]     * kk.x;
                s1 += q[4 * c + 1] * kk.y;
                s2 += q[4 * c + 2] * kk.z;
                s3 += q[4 * c + 3] * kk.w;
            }
            float s = ((s0 + s1) + (s2 + s3)) * 0.125f;
            if (s <= mr) {
                float p = __expf(s - mr);
                l += p;
#pragma unroll
                for (int c = 0; c < 16; c++) {
                    float4 vv = Vs[j][c];
                    o[4 * c]     += p * vv.x;
                    o[4 * c + 1] += p * vv.y;
                    o[4 * c + 2] += p * vv.z;
                    o[4 * c + 3] += p * vv.w;
                }
            } else {
                float r = __expf(mr - s);
                mr = s;
                l = l * r + 1.f;
#pragma unroll
                for (int c = 0; c < 16; c++) {
                    float4 vv = Vs[j][c];
                    o[4 * c]     = o[4 * c]     * r + vv.x;
                    o[4 * c + 1] = o[4 * c + 1] * r + vv.y;
                    o[4 * c + 2] = o[4 * c + 2] * r + vv.z;
                    o[4 * c + 3] = o[4 * c + 3] * r + vv.w;
                }
            }
        }
    }
    float inv = 1.f / l;
    float4* op = (float4*)(HS + (size_t)(bt * NN + n) * 512 + h * HD);
#pragma unroll
    for (int i = 0; i < 16; i++)
        op[i] = make_float4(o[4 * i] * inv, o[4 * i + 1] * inv,
                            o[4 * i + 2] * inv, o[4 * i + 3] * inv);
}

// ---------------- temporal attention (causal over T=24) ----------------
__global__ void __launch_bounds__(192) temporal_attn_k(const float* __restrict__ P,
                                                       float* __restrict__ HT)
{
    const int n = blockIdx.x;
    const int b = blockIdx.y;
    const int h = threadIdx.x & 7;
    const int t = threadIdx.x >> 3;          // 0..23

    float q[64];
    {
        const float4* qp = (const float4*)(P + ((size_t)(b * TT + t) * NN + n) * C3 + 1536 + h * HD);
#pragma unroll
        for (int i = 0; i < 16; i++) {
            float4 v = __ldg(qp + i);
            q[4 * i] = v.x; q[4 * i + 1] = v.y; q[4 * i + 2] = v.z; q[4 * i + 3] = v.w;
        }
    }
    float o[64];
#pragma unroll
    for (int i = 0; i < 64; i++) o[i] = 0.f;
    float mr = -1e30f, l = 0.f;

    for (int s = 0; s <= t; s++) {
        size_t rk = ((size_t)(b * TT + s) * NN + n) * C3;
        const float4* kp = (const float4*)(P + rk + 2048 + h * HD);
        const float4* vp = (const float4*)(P + rk + 2560 + h * HD);
        float s0 = 0.f, s1 = 0.f, s2 = 0.f, s3 = 0.f;
#pragma unroll
        for (int c = 0; c < 16; c++) {
            float4 kk = __ldg(kp + c);
            s0 += q[4 * c]     * kk.x;
            s1 += q[4 * c + 1] * kk.y;
            s2 += q[4 * c + 2] * kk.z;
            s3 += q[4 * c + 3] * kk.w;
        }
        float sc = ((s0 + s1) + (s2 + s3)) * 0.125f;
        if (sc <= mr) {
            float p = __expf(sc - mr);
            l += p;
#pragma unroll
            for (int c = 0; c < 16; c++) {
                float4 vv = __ldg(vp + c);
                o[4 * c]     += p * vv.x;
                o[4 * c + 1] += p * vv.y;
                o[4 * c + 2] += p * vv.z;
                o[4 * c + 3] += p * vv.w;
            }
        } else {
            float r = __expf(mr - sc);
            mr = sc;
            l = l * r + 1.f;
#pragma unroll
            for (int c = 0; c < 16; c++) {
                float4 vv = __ldg(vp + c);
                o[4 * c]     = o[4 * c]     * r + vv.x;
                o[4 * c + 1] = o[4 * c + 1] * r + vv.y;
                o[4 * c + 2] = o[4 * c + 2] * r + vv.z;
                o[4 * c + 3] = o[4 * c + 3] * r + vv.w;
            }
        }
    }
    float inv = 1.f / l;
    float4* op = (float4*)(HT + ((size_t)(b * TT + t) * NN + n) * 512 + h * HD);
#pragma unroll
    for (int i = 0; i < 16; i++)
        op[i] = make_float4(o[4 * i] * inv, o[4 * i + 1] * inv,
                            o[4 * i + 2] * inv, o[4 * i + 3] * inv);
}

// ---------------- launch ----------------
extern "C" void kernel_launch(void* const* d_in, const int* in_sizes, int n_in,
                              void* d_out, int out_size)
{
    const float* X    = (const float*)d_in[0];
    const float* STE  = (const float*)d_in[1];
    const float* sWq  = (const float*)d_in[2];
    const float* sbq  = (const float*)d_in[3];
    const float* sWk  = (const float*)d_in[4];
    const float* sbk  = (const float*)d_in[5];
    const float* sWv  = (const float*)d_in[6];
    const float* sbv  = (const float*)d_in[7];
    const float* sWo  = (const float*)d_in[8];
    const float* sbo  = (const float*)d_in[9];
    const float* tWq  = (const float*)d_in[10];
    const float* tbq  = (const float*)d_in[11];
    const float* tWk  = (const float*)d_in[12];
    const float* tbk  = (const float*)d_in[13];
    const float* tWv  = (const float*)d_in[14];
    const float* tbv  = (const float*)d_in[15];
    const float* tWo  = (const float*)d_in[16];
    const float* tbo  = (const float*)d_in[17];
    const float* gWxs = (const float*)d_in[18];
    const float* gWxt = (const float*)d_in[19];
    const float* gbxt = (const float*)d_in[20];
    const float* gWh1 = (const float*)d_in[21];
    const float* gbh1 = (const float*)d_in[22];
    const float* gWh2 = (const float*)d_in[23];
    const float* gbh2 = (const float*)d_in[24];
    float* out = (float*)d_out;

    float *P, *Wcat, *bcat, *Wg, *HS, *HT, *HST;
    cudaGetSymbolAddress((void**)&P,    g_P);
    cudaGetSymbolAddress((void**)&Wcat, g_Wcat);
    cudaGetSymbolAddress((void**)&bcat, g_bcat);
    cudaGetSymbolAddress((void**)&Wg,   g_Wg);
    cudaGetSymbolAddress((void**)&HS,   g_HS);
    cudaGetSymbolAddress((void**)&HT,   g_HT);
    cudaGetSymbolAddress((void**)&HST,  g_HST);

    // 1) concatenated weights
    concat_w_k<<<(1536 * 3072 + 255) / 256, 256>>>(sWq, sWk, sWv, tWq, tWk, tWv,
                                                   sbq, sbk, sbv, tbq, tbk, tbv,
                                                   Wcat, bcat);
    concat_wg_k<<<(1024 * 512 + 255) / 256, 256>>>(gWxs, gWxt, Wg);

    // 2) all six projections in one GEMM, A = [X|STE] read in-place
    gemm_h_k<1, 1><<<dim3(24, 192), 256>>>(X, STE, Wcat, bcat, nullptr, P,
                                           MROWS, 3072, 1536, 0, 3072, 3072, 0);

    // 3) attention
    spatial_attn_k<<<BB * TT * NH * 2, 256>>>(P, HS);
    temporal_attn_k<<<dim3(NN, BB), 192>>>(P, HT);

    // 4) output projections into HST = [relu(HS@sWo+b) | relu(HT@tWo+b)]
    gemm_h_k<1, 0><<<dim3(4, 192), 256>>>(HS, nullptr, sWo, sbo, nullptr, HST,
                                          MROWS, 512, 512, 512, 512, 1024, 0);
    gemm_h_k<1, 0><<<dim3(4, 192), 256>>>(HT, nullptr, tWo, tbo, nullptr, HST + 512,
                                          MROWS, 512, 512, 512, 512, 1024, 0);

    // 5) gated fusion fused in the epilogue:
    //    H1 = sig(HST@Wg + gbxt) * HSp + (1-sig) * HTp   (into HT buffer)
    gemm_h_k<3, 0><<<dim3(4, 192), 256>>>(HST, nullptr, Wg, gbxt, HST, HT,
                                          MROWS, 512, 1024, 1024, 512, 512, 1024);

    // 6) MLP: H2 = relu(H1 @ gWh1 + gbh1)  (into HS buffer)
    gemm_h_k<1, 0><<<dim3(4, 192), 256>>>(HT, nullptr, gWh1, gbh1, nullptr, HS,
                                          MROWS, 512, 512, 512, 512, 512, 0);
    // out = X + H2 @ gWh2 + gbh2
    gemm_h_k<2, 0><<<dim3(4, 192), 256>>>(HS, nullptr, gWh2, gbh2, X, out,
                                          MROWS, 512, 512, 512, 512, 512, 512);
}

// round 6
// speedup vs baseline: 3.5894x; 1.3765x over previous
#include <cuda_runtime.h>
#include <cuda_fp16.h>
#include <mma.h>
using namespace nvcuda;

// ---------------- problem constants ----------------
#define BB 2
#define TT 24
#define NN 512
#define DD 512
#define NH 8
#define HD 64
#define MROWS (BB*TT*NN)      // 24576
#define C3 3072               // P row stride: [sQ sK sV tQ tK tV]

// ---------------- scratch (static device globals; no allocation) ----------------
__device__ float g_P  [(size_t)MROWS * 3072];   // all six projections, relu'd
__device__ float g_Wcat[1536 * 3072];
__device__ float g_bcat[3072];
__device__ float g_Wg  [1024 * 512];
__device__ float g_HS [(size_t)MROWS * 512];
__device__ float g_HT [(size_t)MROWS * 512];
__device__ float g_HST[(size_t)MROWS * 1024];

// ---------------- weight concat kernels ----------------
__global__ void concat_w_k(const float* __restrict__ w0, const float* __restrict__ w1,
                           const float* __restrict__ w2, const float* __restrict__ w3,
                           const float* __restrict__ w4, const float* __restrict__ w5,
                           const float* __restrict__ b0, const float* __restrict__ b1,
                           const float* __restrict__ b2, const float* __restrict__ b3,
                           const float* __restrict__ b4, const float* __restrict__ b5,
                           float* __restrict__ Wc, float* __restrict__ bc)
{
    int idx = blockIdx.x * blockDim.x + threadIdx.x;
    if (idx < 1536 * 3072) {
        int k = idx / 3072, n = idx % 3072;
        int j = n >> 9, c = n & 511;
        const float* ws[6] = {w0, w1, w2, w3, w4, w5};
        Wc[idx] = ws[j][k * 512 + c];
    }
    if (idx < 3072) {
        int j = idx >> 9, c = idx & 511;
        const float* bs[6] = {b0, b1, b2, b3, b4, b5};
        bc[idx] = bs[j][c];
    }
}

__global__ void concat_wg_k(const float* __restrict__ wxs, const float* __restrict__ wxt,
                            float* __restrict__ Wg)
{
    int idx = blockIdx.x * blockDim.x + threadIdx.x;
    if (idx >= 1024 * 512) return;
    int k = idx / 512, c = idx % 512;
    Wg[idx] = (k < 512) ? wxs[k * 512 + c] : wxt[(k - 512) * 512 + c];
}

__device__ __forceinline__ uint2 f4_to_h4(float4 v) {
    __half2 a = __floats2half2_rn(v.x, v.y);
    __half2 b = __floats2half2_rn(v.z, v.w);
    uint2 r;
    r.x = *(unsigned*)&a;
    r.y = *(unsigned*)&b;
    return r;
}

// ---------------- fp16 tensor-core GEMM 128x128, BK=16 double-buffered ----------------
#define A_LDH 24
#define B_LDH 136
#define AS_STRIDE (128 * A_LDH)
#define BS_STRIDE (16 * B_LDH)
#define SMEM_BYTES 41984

template<int AMODE>
__device__ __forceinline__ float4 ldA(const float* __restrict__ A,
                                      const float* __restrict__ A2,
                                      int m, int c, int lda)
{
    if (AMODE == 1) {
        if (c < 512) return *(const float4*)(A  + (size_t)m * 512  + c);
        else         return *(const float4*)(A2 + (size_t)m * 1024 + (c - 512));
    }
    return *(const float4*)(A + (size_t)m * lda + c);
}

template<int ACT, int AMODE>
__global__ void __launch_bounds__(256, 2) gemm_h_k(
    const float* __restrict__ A, const float* __restrict__ A2,
    const float* __restrict__ B,
    const float* __restrict__ bias, const float* __restrict__ R,
    float* __restrict__ C, int M, int N, int K, int lda, int ldb, int ldc, int ldr)
{
    __shared__ __align__(16) char smem_raw[SMEM_BYTES];
    __half* As = (__half*)smem_raw;
    __half* Bs = (__half*)smem_raw + 2 * AS_STRIDE;

    const int tid  = threadIdx.x;
    const int warp = tid >> 5;
    const int lane = tid & 31;
    const int wm   = warp & 3;
    const int wn   = warp >> 2;
    const int m0 = blockIdx.y * 128;
    const int n0 = blockIdx.x * 128;

    const int a_row = tid >> 2;
    const int a_c4  = (tid & 3) << 2;
    const int b_row = tid >> 5;
    const int b_c4  = (tid & 31) << 2;

    wmma::fragment<wmma::accumulator, 16, 16, 16, float> acc[2][4];
#pragma unroll
    for (int i = 0; i < 2; i++)
#pragma unroll
        for (int j = 0; j < 4; j++) wmma::fill_fragment(acc[i][j], 0.f);

    {
        float4 va0 = ldA<AMODE>(A, A2, m0 + a_row,      a_c4, lda);
        float4 va1 = ldA<AMODE>(A, A2, m0 + 64 + a_row, a_c4, lda);
        float4 vb0 = *(const float4*)(B + (size_t)b_row * ldb + n0 + b_c4);
        float4 vb1 = *(const float4*)(B + (size_t)(8 + b_row) * ldb + n0 + b_c4);
        *(uint2*)(As + a_row * A_LDH + a_c4)        = f4_to_h4(va0);
        *(uint2*)(As + (64 + a_row) * A_LDH + a_c4) = f4_to_h4(va1);
        *(uint2*)(Bs + b_row * B_LDH + b_c4)        = f4_to_h4(vb0);
        *(uint2*)(Bs + (8 + b_row) * B_LDH + b_c4)  = f4_to_h4(vb1);
    }
    __syncthreads();

    const int nk = K >> 4;
    for (int kt = 0; kt < nk; kt++) {
        const int buf = kt & 1;
        float4 pa0, pa1, pb0, pb1;
        const bool pref = (kt + 1 < nk);
        if (pref) {
            int k0 = (kt + 1) << 4;
            pa0 = ldA<AMODE>(A, A2, m0 + a_row,      k0 + a_c4, lda);
            pa1 = ldA<AMODE>(A, A2, m0 + 64 + a_row, k0 + a_c4, lda);
            pb0 = *(const float4*)(B + (size_t)(k0 + b_row) * ldb + n0 + b_c4);
            pb1 = *(const float4*)(B + (size_t)(k0 + 8 + b_row) * ldb + n0 + b_c4);
        }

        const __half* Ab = As + buf * AS_STRIDE;
        const __half* Bb = Bs + buf * BS_STRIDE;

        wmma::fragment<wmma::matrix_a, 16, 16, 16, __half, wmma::row_major> af[2];
#pragma unroll
        for (int fm = 0; fm < 2; fm++)
            wmma::load_matrix_sync(af[fm], Ab + (wm * 32 + fm * 16) * A_LDH, A_LDH);
#pragma unroll
        for (int fn = 0; fn < 4; fn++) {
            wmma::fragment<wmma::matrix_b, 16, 16, 16, __half, wmma::row_major> bf;
            wmma::load_matrix_sync(bf, Bb + wn * 64 + fn * 16, B_LDH);
#pragma unroll
            for (int fm = 0; fm < 2; fm++)
                wmma::mma_sync(acc[fm][fn], af[fm], bf, acc[fm][fn]);
        }

        if (pref) {
            __half* An = As + (buf ^ 1) * AS_STRIDE;
            __half* Bn = Bs + (buf ^ 1) * BS_STRIDE;
            *(uint2*)(An + a_row * A_LDH + a_c4)        = f4_to_h4(pa0);
            *(uint2*)(An + (64 + a_row) * A_LDH + a_c4) = f4_to_h4(pa1);
            *(uint2*)(Bn + b_row * B_LDH + b_c4)        = f4_to_h4(pb0);
            *(uint2*)(Bn + (8 + b_row) * B_LDH + b_c4)  = f4_to_h4(pb1);
        }
        __syncthreads();
    }

    float* sw = (float*)smem_raw + warp * (32 * 40);
#pragma unroll
    for (int h = 0; h < 2; h++) {
#pragma unroll
        for (int fm = 0; fm < 2; fm++)
#pragma unroll
            for (int fnl = 0; fnl < 2; fnl++)
                wmma::store_matrix_sync(sw + fm * 16 * 40 + fnl * 16,
                                        acc[fm][h * 2 + fnl], 40, wmma::mem_row_major);
        __syncwarp();
        const int colbase = n0 + wn * 64 + h * 32;
#pragma unroll
        for (int i = 0; i < 8; i++) {
            int idx = lane + i * 32;
            int r  = idx >> 3;
            int c4 = (idx & 7) << 2;
            float4 v = *(float4*)(sw + r * 40 + c4);
            int row = m0 + wm * 32 + r;
            int col = colbase + c4;
            float4 bv = *(const float4*)(bias + col);
            v.x += bv.x; v.y += bv.y; v.z += bv.z; v.w += bv.w;
            if (ACT == 1) {
                v.x = fmaxf(v.x, 0.f); v.y = fmaxf(v.y, 0.f);
                v.z = fmaxf(v.z, 0.f); v.w = fmaxf(v.w, 0.f);
            }
            if (ACT == 2) {
                float4 rv = *(const float4*)(R + (size_t)row * ldr + col);
                v.x += rv.x; v.y += rv.y; v.z += rv.z; v.w += rv.w;
            }
            if (ACT == 3) {
                float4 hs = *(const float4*)(R + (size_t)row * ldr + col);
                float4 ht = *(const float4*)(R + (size_t)row * ldr + 512 + col);
                float zx = 1.f / (1.f + __expf(-v.x));
                float zy = 1.f / (1.f + __expf(-v.y));
                float zz = 1.f / (1.f + __expf(-v.z));
                float zw = 1.f / (1.f + __expf(-v.w));
                v.x = zx * hs.x + (1.f - zx) * ht.x;
                v.y = zy * hs.y + (1.f - zy) * ht.y;
                v.z = zz * hs.z + (1.f - zz) * ht.z;
                v.w = zw * hs.w + (1.f - zw) * ht.w;
            }
            *(float4*)(C + (size_t)row * ldc + col) = v;
        }
        __syncwarp();
    }
}

// ---------------- spatial attention: wmma flash ----------------
// block = (q-tile of 128, head, bt); 8 warps; warp owns 16 q rows.
// smem: Qs 128x72 h | Ks 64x72 h | Vs 64x72 h | Sc 8x(16x68) f | Ps 8x(16x72) h
#define SA_QS_OFF   0
#define SA_KS_OFF   18432
#define SA_VS_OFF   (18432 + 9216)
#define SA_SC_OFF   36864
#define SA_PS_OFF   (36864 + 34816)
#define SA_SMEM     90112

__global__ void __launch_bounds__(256, 2) spatial_attn_wmma_k(const float* __restrict__ P,
                                                              float* __restrict__ HS)
{
    extern __shared__ __align__(16) char dsm[];
    __half* Qs = (__half*)(dsm + SA_QS_OFF);   // [128][72]
    __half* Ks = (__half*)(dsm + SA_KS_OFF);   // [64][72]
    __half* Vs = (__half*)(dsm + SA_VS_OFF);   // [64][72]
    float*  Sc = (float*)(dsm + SA_SC_OFF);    // 8 x [16][68]
    __half* Ps = (__half*)(dsm + SA_PS_OFF);   // 8 x [16][72]

    const int tid  = threadIdx.x;
    const int w    = tid >> 5;
    const int lane = tid & 31;
    const int q0   = blockIdx.x * 128;
    const int h    = blockIdx.y;
    const int bt   = blockIdx.z;

    const float* base = P + (size_t)bt * NN * C3;

    // load Q tile (128x64) -> fp16 smem
    for (int idx = tid; idx < 2048; idx += 256) {
        int row = idx >> 4, c4 = (idx & 15) << 2;
        float4 v = *(const float4*)(base + (size_t)(q0 + row) * C3 + h * HD + c4);
        *(uint2*)(Qs + row * 72 + c4) = f4_to_h4(v);
    }
    __syncthreads();

    // warp-resident Q fragments (rows w*16..w*16+15, K=64)
    wmma::fragment<wmma::matrix_a, 16, 16, 16, __half, wmma::row_major> qf[4];
#pragma unroll
    for (int i = 0; i < 4; i++)
        wmma::load_matrix_sync(qf[i], Qs + (w * 16) * 72 + i * 16, 72);

    float* Sw  = Sc + w * 1088;        // [16][68]
    __half* Pw = Ps + w * 1152;        // [16][72]
    const int r  = lane >> 1;
    const int hf = lane & 1;

    float Oreg[32];
#pragma unroll
    for (int i = 0; i < 32; i++) Oreg[i] = 0.f;
    float m = -1e30f, l = 0.f;

    for (int tile = 0; tile < 8; tile++) {
        __syncthreads();   // all warps done reading previous Ks/Vs
        // load K/V tile (64x64 each)
        for (int idx = tid; idx < 1024; idx += 256) {
            int row = idx >> 4, c4 = (idx & 15) << 2;
            const float* rp = base + (size_t)(tile * 64 + row) * C3 + h * HD + c4;
            *(uint2*)(Ks + row * 72 + c4) = f4_to_h4(*(const float4*)(rp + 512));
            *(uint2*)(Vs + row * 72 + c4) = f4_to_h4(*(const float4*)(rp + 1024));
        }
        __syncthreads();

        // S = Q @ K^T  (16 x 64)
        wmma::fragment<wmma::accumulator, 16, 16, 16, float> sf[4];
#pragma unroll
        for (int j = 0; j < 4; j++) wmma::fill_fragment(sf[j], 0.f);
#pragma unroll
        for (int i = 0; i < 4; i++) {
#pragma unroll
            for (int j = 0; j < 4; j++) {
                wmma::fragment<wmma::matrix_b, 16, 16, 16, __half, wmma::col_major> bf;
                wmma::load_matrix_sync(bf, Ks + (j * 16) * 72 + i * 16, 72);
                wmma::mma_sync(sf[j], qf[i], bf, sf[j]);
            }
        }
#pragma unroll
        for (int j = 0; j < 4; j++)
            wmma::store_matrix_sync(Sw + j * 16, sf[j], 68, wmma::mem_row_major);
        __syncwarp();

        // online softmax: thread owns row r, cols hf*32..+31
        const float* srow = Sw + r * 68 + hf * 32;
        float mx = -1e30f;
#pragma unroll
        for (int j = 0; j < 32; j++) mx = fmaxf(mx, srow[j]);
        mx = fmaxf(mx, __shfl_xor_sync(0xffffffffu, mx, 1));
        float tm = mx * 0.125f;
        float nm = fmaxf(m, tm);
        float rf = __expf(m - nm);
#pragma unroll
        for (int j = 0; j < 32; j++) Oreg[j] *= rf;
        float ps = 0.f;
        __half* prow = Pw + r * 72 + hf * 32;
#pragma unroll
        for (int j = 0; j < 32; j += 2) {
            float p0 = __expf(srow[j] * 0.125f - nm);
            float p1 = __expf(srow[j + 1] * 0.125f - nm);
            ps += p0 + p1;
            *(__half2*)(prow + j) = __floats2half2_rn(p0, p1);
        }
        ps += __shfl_xor_sync(0xffffffffu, ps, 1);
        l = l * rf + ps;
        m = nm;
        __syncwarp();

        // O += P @ V  (16 x 64)
        wmma::fragment<wmma::accumulator, 16, 16, 16, float> of[4];
#pragma unroll
        for (int j = 0; j < 4; j++) wmma::fill_fragment(of[j], 0.f);
#pragma unroll
        for (int i = 0; i < 4; i++) {
            wmma::fragment<wmma::matrix_a, 16, 16, 16, __half, wmma::row_major> af;
            wmma::load_matrix_sync(af, Pw + i * 16, 72);
#pragma unroll
            for (int j = 0; j < 4; j++) {
                wmma::fragment<wmma::matrix_b, 16, 16, 16, __half, wmma::row_major> bf;
                wmma::load_matrix_sync(bf, Vs + (i * 16) * 72 + j * 16, 72);
                wmma::mma_sync(of[j], af, bf, of[j]);
            }
        }
#pragma unroll
        for (int j = 0; j < 4; j++)
            wmma::store_matrix_sync(Sw + j * 16, of[j], 68, wmma::mem_row_major);
        __syncwarp();
        const float* orow = Sw + r * 68 + hf * 32;
#pragma unroll
        for (int j = 0; j < 32; j++) Oreg[j] += orow[j];
        __syncwarp();
    }

    float inv = 1.f / l;
    float* op = HS + (size_t)(bt * NN + q0 + w * 16 + r) * 512 + h * HD + hf * 32;
#pragma unroll
    for (int i = 0; i < 8; i++)
        *(float4*)(op + i * 4) = make_float4(Oreg[4 * i] * inv, Oreg[4 * i + 1] * inv,
                                             Oreg[4 * i + 2] * inv, Oreg[4 * i + 3] * inv);
}

// ---------------- temporal attention (causal over T=24) ----------------
__global__ void __launch_bounds__(192) temporal_attn_k(const float* __restrict__ P,
                                                       float* __restrict__ HT)
{
    const int n = blockIdx.x;
    const int b = blockIdx.y;
    const int h = threadIdx.x & 7;
    const int t = threadIdx.x >> 3;

    float q[64];
    {
        const float4* qp = (const float4*)(P + ((size_t)(b * TT + t) * NN + n) * C3 + 1536 + h * HD);
#pragma unroll
        for (int i = 0; i < 16; i++) {
            float4 v = __ldg(qp + i);
            q[4 * i] = v.x; q[4 * i + 1] = v.y; q[4 * i + 2] = v.z; q[4 * i + 3] = v.w;
        }
    }
    float o[64];
#pragma unroll
    for (int i = 0; i < 64; i++) o[i] = 0.f;
    float mr = -1e30f, l = 0.f;

    for (int s = 0; s <= t; s++) {
        size_t rk = ((size_t)(b * TT + s) * NN + n) * C3;
        const float4* kp = (const float4*)(P + rk + 2048 + h * HD);
        const float4* vp = (const float4*)(P + rk + 2560 + h * HD);
        float s0 = 0.f, s1 = 0.f, s2 = 0.f, s3 = 0.f;
#pragma unroll
        for (int c = 0; c < 16; c++) {
            float4 kk = __ldg(kp + c);
            s0 += q[4 * c]     * kk.x;
            s1 += q[4 * c + 1] * kk.y;
            s2 += q[4 * c + 2] * kk.z;
            s3 += q[4 * c + 3] * kk.w;
        }
        float sc = ((s0 + s1) + (s2 + s3)) * 0.125f;
        if (sc <= mr) {
            float p = __expf(sc - mr);
            l += p;
#pragma unroll
            for (int c = 0; c < 16; c++) {
                float4 vv = __ldg(vp + c);
                o[4 * c]     += p * vv.x;
                o[4 * c + 1] += p * vv.y;
                o[4 * c + 2] += p * vv.z;
                o[4 * c + 3] += p * vv.w;
            }
        } else {
            float r = __expf(mr - sc);
            mr = sc;
            l = l * r + 1.f;
#pragma unroll
            for (int c = 0; c < 16; c++) {
                float4 vv = __ldg(vp + c);
                o[4 * c]     = o[4 * c]     * r + vv.x;
                o[4 * c + 1] = o[4 * c + 1] * r + vv.y;
                o[4 * c + 2] = o[4 * c + 2] * r + vv.z;
                o[4 * c + 3] = o[4 * c + 3] * r + vv.w;
            }
        }
    }
    float inv = 1.f / l;
    float4* op = (float4*)(HT + ((size_t)(b * TT + t) * NN + n) * 512 + h * HD);
#pragma unroll
    for (int i = 0; i < 16; i++)
        op[i] = make_float4(o[4 * i] * inv, o[4 * i + 1] * inv,
                            o[4 * i + 2] * inv, o[4 * i + 3] * inv);
}

// ---------------- launch ----------------
extern "C" void kernel_launch(void* const* d_in, const int* in_sizes, int n_in,
                              void* d_out, int out_size)
{
    const float* X    = (const float*)d_in[0];
    const float* STE  = (const float*)d_in[1];
    const float* sWq  = (const float*)d_in[2];
    const float* sbq  = (const float*)d_in[3];
    const float* sWk  = (const float*)d_in[4];
    const float* sbk  = (const float*)d_in[5];
    const float* sWv  = (const float*)d_in[6];
    const float* sbv  = (const float*)d_in[7];
    const float* sWo  = (const float*)d_in[8];
    const float* sbo  = (const float*)d_in[9];
    const float* tWq  = (const float*)d_in[10];
    const float* tbq  = (const float*)d_in[11];
    const float* tWk  = (const float*)d_in[12];
    const float* tbk  = (const float*)d_in[13];
    const float* tWv  = (const float*)d_in[14];
    const float* tbv  = (const float*)d_in[15];
    const float* tWo  = (const float*)d_in[16];
    const float* tbo  = (const float*)d_in[17];
    const float* gWxs = (const float*)d_in[18];
    const float* gWxt = (const float*)d_in[19];
    const float* gbxt = (const float*)d_in[20];
    const float* gWh1 = (const float*)d_in[21];
    const float* gbh1 = (const float*)d_in[22];
    const float* gWh2 = (const float*)d_in[23];
    const float* gbh2 = (const float*)d_in[24];
    float* out = (float*)d_out;

    float *P, *Wcat, *bcat, *Wg, *HS, *HT, *HST;
    cudaGetSymbolAddress((void**)&P,    g_P);
    cudaGetSymbolAddress((void**)&Wcat, g_Wcat);
    cudaGetSymbolAddress((void**)&bcat, g_bcat);
    cudaGetSymbolAddress((void**)&Wg,   g_Wg);
    cudaGetSymbolAddress((void**)&HS,   g_HS);
    cudaGetSymbolAddress((void**)&HT,   g_HT);
    cudaGetSymbolAddress((void**)&HST,  g_HST);

    static int sa_attr_set = 0;
    if (!sa_attr_set) {
        cudaFuncSetAttribute(spatial_attn_wmma_k,
                             cudaFuncAttributeMaxDynamicSharedMemorySize, SA_SMEM);
        sa_attr_set = 1;
    }

    // 1) concatenated weights
    concat_w_k<<<(1536 * 3072 + 255) / 256, 256>>>(sWq, sWk, sWv, tWq, tWk, tWv,
                                                   sbq, sbk, sbv, tbq, tbk, tbv,
                                                   Wcat, bcat);
    concat_wg_k<<<(1024 * 512 + 255) / 256, 256>>>(gWxs, gWxt, Wg);

    // 2) all six projections in one GEMM, A = [X|STE] read in-place
    gemm_h_k<1, 1><<<dim3(24, 192), 256>>>(X, STE, Wcat, bcat, nullptr, P,
                                           MROWS, 3072, 1536, 0, 3072, 3072, 0);

    // 3) attention
    spatial_attn_wmma_k<<<dim3(4, NH, BB * TT), 256, SA_SMEM>>>(P, HS);
    temporal_attn_k<<<dim3(NN, BB), 192>>>(P, HT);

    // 4) output projections into HST = [relu(HS@sWo+b) | relu(HT@tWo+b)]
    gemm_h_k<1, 0><<<dim3(4, 192), 256>>>(HS, nullptr, sWo, sbo, nullptr, HST,
                                          MROWS, 512, 512, 512, 512, 1024, 0);
    gemm_h_k<1, 0><<<dim3(4, 192), 256>>>(HT, nullptr, tWo, tbo, nullptr, HST + 512,
                                          MROWS, 512, 512, 512, 512, 1024, 0);

    // 5) gated fusion fused in the epilogue
    gemm_h_k<3, 0><<<dim3(4, 192), 256>>>(HST, nullptr, Wg, gbxt, HST, HT,
                                          MROWS, 512, 1024, 1024, 512, 512, 1024);

    // 6) MLP
    gemm_h_k<1, 0><<<dim3(4, 192), 256>>>(HT, nullptr, gWh1, gbh1, nullptr, HS,
                                          MROWS, 512, 512, 512, 512, 512, 0);
    gemm_h_k<2, 0><<<dim3(4, 192), 256>>>(HS, nullptr, gWh2, gbh2, X, out,
                                          MROWS, 512, 512, 512, 512, 512, 512);
}

// round 7
// speedup vs baseline: 5.0581x; 1.4092x over previous
#include <cuda_runtime.h>
#include <cuda_fp16.h>
#include <mma.h>
using namespace nvcuda;

// ---------------- problem constants ----------------
#define BB 2
#define TT 24
#define NN 512
#define DD 512
#define NH 8
#define HD 64
#define MROWS (BB*TT*NN)      // 24576
#define C3 3072               // P row stride: [sQ sK sV tQ tK tV]

// ---------------- scratch (static device globals; no allocation) ----------------
__device__ __half g_Xh [(size_t)MROWS * 1536];   // concat(X, STE) fp16
__device__ __half g_Ph [(size_t)MROWS * 3072];   // six projections, relu'd, fp16
__device__ __half g_Wch[1536 * 3072];
__device__ float  g_bcat[3072];
__device__ __half g_Wgh[1024 * 512];
__device__ __half g_sWoh[512 * 512];
__device__ __half g_tWoh[512 * 512];
__device__ __half g_Wh1h[512 * 512];
__device__ __half g_Wh2h[512 * 512];
__device__ __half g_HSh [(size_t)MROWS * 512];
__device__ __half g_HTh [(size_t)MROWS * 512];
__device__ __half g_HSTh[(size_t)MROWS * 1024];

__device__ __forceinline__ uint2 f4_to_h4(float4 v) {
    __half2 a = __floats2half2_rn(v.x, v.y);
    __half2 b = __floats2half2_rn(v.z, v.w);
    uint2 r;
    r.x = *(unsigned*)&a;
    r.y = *(unsigned*)&b;
    return r;
}

__device__ __forceinline__ void h8_to_f8(uint4 u, float* f) {
    __half2* h = (__half2*)&u;
#pragma unroll
    for (int i = 0; i < 4; i++) {
        float2 t = __half22float2(h[i]);
        f[2 * i] = t.x; f[2 * i + 1] = t.y;
    }
}

// ---------------- conversion / concat kernels ----------------
__global__ void conv_xc_h(const float* __restrict__ X, const float* __restrict__ STE,
                          __half* __restrict__ Xh)
{
    int idx = blockIdx.x * blockDim.x + threadIdx.x;   // float4 units
    if (idx >= MROWS * 384) return;
    int m = idx / 384, c4 = idx % 384;
    float4 v;
    if (c4 < 128) v = ((const float4*)X)[(size_t)m * 128 + c4];
    else          v = ((const float4*)STE)[(size_t)m * 256 + (c4 - 128)];
    *(uint2*)(Xh + (size_t)idx * 4) = f4_to_h4(v);
}

__global__ void concat_w_h(const float* __restrict__ w0, const float* __restrict__ w1,
                           const float* __restrict__ w2, const float* __restrict__ w3,
                           const float* __restrict__ w4, const float* __restrict__ w5,
                           const float* __restrict__ b0, const float* __restrict__ b1,
                           const float* __restrict__ b2, const float* __restrict__ b3,
                           const float* __restrict__ b4, const float* __restrict__ b5,
                           __half* __restrict__ Wc, float* __restrict__ bc)
{
    int idx = blockIdx.x * blockDim.x + threadIdx.x;
    if (idx < 1536 * 3072) {
        int k = idx / 3072, n = idx % 3072;
        int j = n >> 9, c = n & 511;
        const float* ws[6] = {w0, w1, w2, w3, w4, w5};
        Wc[idx] = __float2half(ws[j][k * 512 + c]);
    }
    if (idx < 3072) {
        int j = idx >> 9, c = idx & 511;
        const float* bs[6] = {b0, b1, b2, b3, b4, b5};
        bc[idx] = bs[j][c];
    }
}

__global__ void concat_wg_h(const float* __restrict__ wxs, const float* __restrict__ wxt,
                            __half* __restrict__ Wg)
{
    int idx = blockIdx.x * blockDim.x + threadIdx.x;
    if (idx >= 1024 * 512) return;
    int k = idx / 512, c = idx % 512;
    Wg[idx] = __float2half((k < 512) ? wxs[k * 512 + c] : wxt[(k - 512) * 512 + c]);
}

__global__ void conv4_w_h(const float* __restrict__ w0, const float* __restrict__ w1,
                          const float* __restrict__ w2, const float* __restrict__ w3,
                          __half* __restrict__ o0, __half* __restrict__ o1,
                          __half* __restrict__ o2, __half* __restrict__ o3)
{
    int idx = blockIdx.x * blockDim.x + threadIdx.x;
    if (idx >= 4 * 262144) return;
    int which = idx >> 18, e = idx & 262143;
    const float* w = (which == 0) ? w0 : (which == 1) ? w1 : (which == 2) ? w2 : w3;
    __half* o = (which == 0) ? o0 : (which == 1) ? o1 : (which == 2) ? o2 : o3;
    o[e] = __float2half(w[e]);
}

// ---------------- fp16-in fp16/fp32-out tensor GEMM 128x128, BK=32 ----------------
// ACT: 0 bias, 1 bias+relu, 2 bias+residual(float R), 3 gated fusion(half R)
#define GA_LDH 40
#define GB_LDH 136
#define GAS (128 * GA_LDH)   // 5120 halves / stage
#define GBS (32 * GB_LDH)    // 4352 halves / stage
#define GSMEM 41984

template<int ACT, typename OutT>
__global__ void __launch_bounds__(256, 2) gemm_hh_k(
    const __half* __restrict__ A, const __half* __restrict__ B,
    const float* __restrict__ bias, const void* __restrict__ Rv,
    OutT* __restrict__ C, int M, int N, int K, int lda, int ldb, int ldc, int ldr)
{
    __shared__ __align__(16) char smem_raw[GSMEM];
    __half* As = (__half*)smem_raw;
    __half* Bs = (__half*)smem_raw + 2 * GAS;

    const int tid  = threadIdx.x;
    const int warp = tid >> 5;
    const int lane = tid & 31;
    const int wm   = warp & 3;
    const int wn   = warp >> 2;
    const int m0 = blockIdx.y * 128;
    const int n0 = blockIdx.x * 128;

    const int a_row = tid >> 2;          // 0..63 (two passes)
    const int a_c8  = (tid & 3) << 3;    // 0,8,16,24
    const int b_row = tid >> 4;          // 0..15 (two passes)
    const int b_c8  = (tid & 15) << 3;   // 0..120

    wmma::fragment<wmma::accumulator, 16, 16, 16, float> acc[2][4];
#pragma unroll
    for (int i = 0; i < 2; i++)
#pragma unroll
        for (int j = 0; j < 4; j++) wmma::fill_fragment(acc[i][j], 0.f);

    // preload stage 0
    {
        *(uint4*)(As + a_row * GA_LDH + a_c8) =
            *(const uint4*)(A + (size_t)(m0 + a_row) * lda + a_c8);
        *(uint4*)(As + (64 + a_row) * GA_LDH + a_c8) =
            *(const uint4*)(A + (size_t)(m0 + 64 + a_row) * lda + a_c8);
        *(uint4*)(Bs + b_row * GB_LDH + b_c8) =
            *(const uint4*)(B + (size_t)b_row * ldb + n0 + b_c8);
        *(uint4*)(Bs + (16 + b_row) * GB_LDH + b_c8) =
            *(const uint4*)(B + (size_t)(16 + b_row) * ldb + n0 + b_c8);
    }
    __syncthreads();

    const int nk = K >> 5;
    for (int kt = 0; kt < nk; kt++) {
        const int buf = kt & 1;
        uint4 pa0, pa1, pb0, pb1;
        const bool pref = (kt + 1 < nk);
        if (pref) {
            int k0 = (kt + 1) << 5;
            pa0 = *(const uint4*)(A + (size_t)(m0 + a_row) * lda + k0 + a_c8);
            pa1 = *(const uint4*)(A + (size_t)(m0 + 64 + a_row) * lda + k0 + a_c8);
            pb0 = *(const uint4*)(B + (size_t)(k0 + b_row) * ldb + n0 + b_c8);
            pb1 = *(const uint4*)(B + (size_t)(k0 + 16 + b_row) * ldb + n0 + b_c8);
        }

        const __half* Ab = As + buf * GAS;
        const __half* Bb = Bs + buf * GBS;
#pragma unroll
        for (int ks = 0; ks < 2; ks++) {
            wmma::fragment<wmma::matrix_a, 16, 16, 16, __half, wmma::row_major> af[2];
#pragma unroll
            for (int fm = 0; fm < 2; fm++)
                wmma::load_matrix_sync(af[fm], Ab + (wm * 32 + fm * 16) * GA_LDH + ks * 16, GA_LDH);
#pragma unroll
            for (int fn = 0; fn < 4; fn++) {
                wmma::fragment<wmma::matrix_b, 16, 16, 16, __half, wmma::row_major> bf;
                wmma::load_matrix_sync(bf, Bb + (ks * 16) * GB_LDH + wn * 64 + fn * 16, GB_LDH);
#pragma unroll
                for (int fm = 0; fm < 2; fm++)
                    wmma::mma_sync(acc[fm][fn], af[fm], bf, acc[fm][fn]);
            }
        }

        if (pref) {
            __half* An = As + (buf ^ 1) * GAS;
            __half* Bn = Bs + (buf ^ 1) * GBS;
            *(uint4*)(An + a_row * GA_LDH + a_c8)        = pa0;
            *(uint4*)(An + (64 + a_row) * GA_LDH + a_c8) = pa1;
            *(uint4*)(Bn + b_row * GB_LDH + b_c8)        = pb0;
            *(uint4*)(Bn + (16 + b_row) * GB_LDH + b_c8) = pb1;
        }
        __syncthreads();
    }

    // epilogue via per-warp fp32 scratch (32 rows x 40 stride)
    float* sw = (float*)smem_raw + warp * (32 * 40);
#pragma unroll
    for (int h = 0; h < 2; h++) {
#pragma unroll
        for (int fm = 0; fm < 2; fm++)
#pragma unroll
            for (int fnl = 0; fnl < 2; fnl++)
                wmma::store_matrix_sync(sw + fm * 16 * 40 + fnl * 16,
                                        acc[fm][h * 2 + fnl], 40, wmma::mem_row_major);
        __syncwarp();
        const int colbase = n0 + wn * 64 + h * 32;
#pragma unroll
        for (int i = 0; i < 8; i++) {
            int idx = lane + i * 32;
            int r  = idx >> 3;
            int c4 = (idx & 7) << 2;
            float4 v = *(float4*)(sw + r * 40 + c4);
            int row = m0 + wm * 32 + r;
            int col = colbase + c4;
            float4 bv = *(const float4*)(bias + col);
            v.x += bv.x; v.y += bv.y; v.z += bv.z; v.w += bv.w;
            if (ACT == 1) {
                v.x = fmaxf(v.x, 0.f); v.y = fmaxf(v.y, 0.f);
                v.z = fmaxf(v.z, 0.f); v.w = fmaxf(v.w, 0.f);
            }
            if (ACT == 2) {
                const float* Rf = (const float*)Rv;
                float4 rv = *(const float4*)(Rf + (size_t)row * ldr + col);
                v.x += rv.x; v.y += rv.y; v.z += rv.z; v.w += rv.w;
            }
            if (ACT == 3) {
                const __half* Rh = (const __half*)Rv;
                float hs[4], ht[4];
                uint2 u1 = *(const uint2*)(Rh + (size_t)row * ldr + col);
                uint2 u2 = *(const uint2*)(Rh + (size_t)row * ldr + 512 + col);
                {
                    __half2* hh = (__half2*)&u1;
                    float2 t0 = __half22float2(hh[0]), t1 = __half22float2(hh[1]);
                    hs[0] = t0.x; hs[1] = t0.y; hs[2] = t1.x; hs[3] = t1.y;
                }
                {
                    __half2* hh = (__half2*)&u2;
                    float2 t0 = __half22float2(hh[0]), t1 = __half22float2(hh[1]);
                    ht[0] = t0.x; ht[1] = t0.y; ht[2] = t1.x; ht[3] = t1.y;
                }
                float zx = 1.f / (1.f + __expf(-v.x));
                float zy = 1.f / (1.f + __expf(-v.y));
                float zz = 1.f / (1.f + __expf(-v.z));
                float zw = 1.f / (1.f + __expf(-v.w));
                v.x = zx * hs[0] + (1.f - zx) * ht[0];
                v.y = zy * hs[1] + (1.f - zy) * ht[1];
                v.z = zz * hs[2] + (1.f - zz) * ht[2];
                v.w = zw * hs[3] + (1.f - zw) * ht[3];
            }
            if constexpr (sizeof(OutT) == 2) {
                *(uint2*)((__half*)C + (size_t)row * ldc + col) = f4_to_h4(v);
            } else {
                *(float4*)((float*)C + (size_t)row * ldc + col) = v;
            }
        }
        __syncwarp();
    }
}

// ---------------- spatial attention: wmma flash (fp16 P) ----------------
#define SA_QS_OFF   0
#define SA_KS_OFF   18432
#define SA_VS_OFF   (18432 + 9216)
#define SA_SC_OFF   36864
#define SA_PS_OFF   (36864 + 34816)
#define SA_SMEM     90112

__global__ void __launch_bounds__(256, 2) spatial_attn_wmma_k(const __half* __restrict__ P,
                                                              __half* __restrict__ HS)
{
    extern __shared__ __align__(16) char dsm[];
    __half* Qs = (__half*)(dsm + SA_QS_OFF);   // [128][72]
    __half* Ks = (__half*)(dsm + SA_KS_OFF);   // [64][72]
    __half* Vs = (__half*)(dsm + SA_VS_OFF);   // [64][72]
    float*  Sc = (float*)(dsm + SA_SC_OFF);    // 8 x [16][68]
    __half* Ps = (__half*)(dsm + SA_PS_OFF);   // 8 x [16][72]

    const int tid  = threadIdx.x;
    const int w    = tid >> 5;
    const int lane = tid & 31;
    const int q0   = blockIdx.x * 128;
    const int h    = blockIdx.y;
    const int bt   = blockIdx.z;

    const __half* base = P + (size_t)bt * NN * C3;

    // load Q tile (128x64 halves) -> smem (raw copy)
    for (int idx = tid; idx < 1024; idx += 256) {
        int row = idx >> 3, c8 = (idx & 7) << 3;
        *(uint4*)(Qs + row * 72 + c8) =
            *(const uint4*)(base + (size_t)(q0 + row) * C3 + h * HD + c8);
    }
    __syncthreads();

    wmma::fragment<wmma::matrix_a, 16, 16, 16, __half, wmma::row_major> qf[4];
#pragma unroll
    for (int i = 0; i < 4; i++)
        wmma::load_matrix_sync(qf[i], Qs + (w * 16) * 72 + i * 16, 72);

    float* Sw  = Sc + w * 1088;
    __half* Pw = Ps + w * 1152;
    const int r  = lane >> 1;
    const int hf = lane & 1;

    float Oreg[32];
#pragma unroll
    for (int i = 0; i < 32; i++) Oreg[i] = 0.f;
    float m = -1e30f, l = 0.f;

    for (int tile = 0; tile < 8; tile++) {
        __syncthreads();
        for (int idx = tid; idx < 512; idx += 256) {
            int row = idx >> 3, c8 = (idx & 7) << 3;
            const __half* rp = base + (size_t)(tile * 64 + row) * C3 + h * HD + c8;
            *(uint4*)(Ks + row * 72 + c8) = *(const uint4*)(rp + 512);
            *(uint4*)(Vs + row * 72 + c8) = *(const uint4*)(rp + 1024);
        }
        __syncthreads();

        wmma::fragment<wmma::accumulator, 16, 16, 16, float> sf[4];
#pragma unroll
        for (int j = 0; j < 4; j++) wmma::fill_fragment(sf[j], 0.f);
#pragma unroll
        for (int i = 0; i < 4; i++) {
#pragma unroll
            for (int j = 0; j < 4; j++) {
                wmma::fragment<wmma::matrix_b, 16, 16, 16, __half, wmma::col_major> bf;
                wmma::load_matrix_sync(bf, Ks + (j * 16) * 72 + i * 16, 72);
                wmma::mma_sync(sf[j], qf[i], bf, sf[j]);
            }
        }
#pragma unroll
        for (int j = 0; j < 4; j++)
            wmma::store_matrix_sync(Sw + j * 16, sf[j], 68, wmma::mem_row_major);
        __syncwarp();

        const float* srow = Sw + r * 68 + hf * 32;
        float mx = -1e30f;
#pragma unroll
        for (int j = 0; j < 32; j++) mx = fmaxf(mx, srow[j]);
        mx = fmaxf(mx, __shfl_xor_sync(0xffffffffu, mx, 1));
        float tm = mx * 0.125f;
        float nm = fmaxf(m, tm);
        float rf = __expf(m - nm);
#pragma unroll
        for (int j = 0; j < 32; j++) Oreg[j] *= rf;
        float ps = 0.f;
        __half* prow = Pw + r * 72 + hf * 32;
#pragma unroll
        for (int j = 0; j < 32; j += 2) {
            float p0 = __expf(srow[j] * 0.125f - nm);
            float p1 = __expf(srow[j + 1] * 0.125f - nm);
            ps += p0 + p1;
            *(__half2*)(prow + j) = __floats2half2_rn(p0, p1);
        }
        ps += __shfl_xor_sync(0xffffffffu, ps, 1);
        l = l * rf + ps;
        m = nm;
        __syncwarp();

        wmma::fragment<wmma::accumulator, 16, 16, 16, float> of[4];
#pragma unroll
        for (int j = 0; j < 4; j++) wmma::fill_fragment(of[j], 0.f);
#pragma unroll
        for (int i = 0; i < 4; i++) {
            wmma::fragment<wmma::matrix_a, 16, 16, 16, __half, wmma::row_major> af;
            wmma::load_matrix_sync(af, Pw + i * 16, 72);
#pragma unroll
            for (int j = 0; j < 4; j++) {
                wmma::fragment<wmma::matrix_b, 16, 16, 16, __half, wmma::row_major> bf;
                wmma::load_matrix_sync(bf, Vs + (i * 16) * 72 + j * 16, 72);
                wmma::mma_sync(of[j], af, bf, of[j]);
            }
        }
#pragma unroll
        for (int j = 0; j < 4; j++)
            wmma::store_matrix_sync(Sw + j * 16, of[j], 68, wmma::mem_row_major);
        __syncwarp();
        const float* orow = Sw + r * 68 + hf * 32;
#pragma unroll
        for (int j = 0; j < 32; j++) Oreg[j] += orow[j];
        __syncwarp();
    }

    float inv = 1.f / l;
    __half* op = HS + (size_t)(bt * NN + q0 + w * 16 + r) * 512 + h * HD + hf * 32;
#pragma unroll
    for (int i = 0; i < 8; i++) {
        float4 v = make_float4(Oreg[4 * i] * inv, Oreg[4 * i + 1] * inv,
                               Oreg[4 * i + 2] * inv, Oreg[4 * i + 3] * inv);
        *(uint2*)(op + i * 4) = f4_to_h4(v);
    }
}

// ---------------- temporal attention (causal over T=24, fp16 P) ----------------
__global__ void __launch_bounds__(192) temporal_attn_k(const __half* __restrict__ P,
                                                       __half* __restrict__ HT)
{
    const int n = blockIdx.x;
    const int b = blockIdx.y;
    const int h = threadIdx.x & 7;
    const int t = threadIdx.x >> 3;

    float q[64];
    {
        const uint4* qp = (const uint4*)(P + ((size_t)(b * TT + t) * NN + n) * C3 + 1536 + h * HD);
#pragma unroll
        for (int i = 0; i < 8; i++) h8_to_f8(__ldg(qp + i), q + 8 * i);
    }
    float o[64];
#pragma unroll
    for (int i = 0; i < 64; i++) o[i] = 0.f;
    float mr = -1e30f, l = 0.f;

    for (int s = 0; s <= t; s++) {
        size_t rk = ((size_t)(b * TT + s) * NN + n) * C3;
        const uint4* kp = (const uint4*)(P + rk + 2048 + h * HD);
        const uint4* vp = (const uint4*)(P + rk + 2560 + h * HD);
        float kb[64];
#pragma unroll
        for (int i = 0; i < 8; i++) h8_to_f8(__ldg(kp + i), kb + 8 * i);
        float s0 = 0.f, s1 = 0.f, s2 = 0.f, s3 = 0.f;
#pragma unroll
        for (int c = 0; c < 16; c++) {
            s0 += q[4 * c]     * kb[4 * c];
            s1 += q[4 * c + 1] * kb[4 * c + 1];
            s2 += q[4 * c + 2] * kb[4 * c + 2];
            s3 += q[4 * c + 3] * kb[4 * c + 3];
        }
        float sc = ((s0 + s1) + (s2 + s3)) * 0.125f;
        float vb[64];
#pragma unroll
        for (int i = 0; i < 8; i++) h8_to_f8(__ldg(vp + i), vb + 8 * i);
        if (sc <= mr) {
            float p = __expf(sc - mr);
            l += p;
#pragma unroll
            for (int c = 0; c < 64; c++) o[c] += p * vb[c];
        } else {
            float r = __expf(mr - sc);
            mr = sc;
            l = l * r + 1.f;
#pragma unroll
            for (int c = 0; c < 64; c++) o[c] = o[c] * r + vb[c];
        }
    }
    float inv = 1.f / l;
    __half* op = HT + ((size_t)(b * TT + t) * NN + n) * 512 + h * HD;
#pragma unroll
    for (int i = 0; i < 16; i++) {
        float4 v = make_float4(o[4 * i] * inv, o[4 * i + 1] * inv,
                               o[4 * i + 2] * inv, o[4 * i + 3] * inv);
        *(uint2*)(op + 4 * i) = f4_to_h4(v);
    }
}

// ---------------- launch ----------------
extern "C" void kernel_launch(void* const* d_in, const int* in_sizes, int n_in,
                              void* d_out, int out_size)
{
    const float* X    = (const float*)d_in[0];
    const float* STE  = (const float*)d_in[1];
    const float* sWq  = (const float*)d_in[2];
    const float* sbq  = (const float*)d_in[3];
    const float* sWk  = (const float*)d_in[4];
    const float* sbk  = (const float*)d_in[5];
    const float* sWv  = (const float*)d_in[6];
    const float* sbv  = (const float*)d_in[7];
    const float* sWo  = (const float*)d_in[8];
    const float* sbo  = (const float*)d_in[9];
    const float* tWq  = (const float*)d_in[10];
    const float* tbq  = (const float*)d_in[11];
    const float* tWk  = (const float*)d_in[12];
    const float* tbk  = (const float*)d_in[13];
    const float* tWv  = (const float*)d_in[14];
    const float* tbv  = (const float*)d_in[15];
    const float* tWo  = (const float*)d_in[16];
    const float* tbo  = (const float*)d_in[17];
    const float* gWxs = (const float*)d_in[18];
    const float* gWxt = (const float*)d_in[19];
    const float* gbxt = (const float*)d_in[20];
    const float* gWh1 = (const float*)d_in[21];
    const float* gbh1 = (const float*)d_in[22];
    const float* gWh2 = (const float*)d_in[23];
    const float* gbh2 = (const float*)d_in[24];
    float* out = (float*)d_out;

    __half *Xh, *Ph, *Wch, *Wgh, *sWoh, *tWoh, *Wh1h, *Wh2h, *HSh, *HTh, *HSTh;
    float *bcat;
    cudaGetSymbolAddress((void**)&Xh,   g_Xh);
    cudaGetSymbolAddress((void**)&Ph,   g_Ph);
    cudaGetSymbolAddress((void**)&Wch,  g_Wch);
    cudaGetSymbolAddress((void**)&bcat, g_bcat);
    cudaGetSymbolAddress((void**)&Wgh,  g_Wgh);
    cudaGetSymbolAddress((void**)&sWoh, g_sWoh);
    cudaGetSymbolAddress((void**)&tWoh, g_tWoh);
    cudaGetSymbolAddress((void**)&Wh1h, g_Wh1h);
    cudaGetSymbolAddress((void**)&Wh2h, g_Wh2h);
    cudaGetSymbolAddress((void**)&HSh,  g_HSh);
    cudaGetSymbolAddress((void**)&HTh,  g_HTh);
    cudaGetSymbolAddress((void**)&HSTh, g_HSTh);

    static int sa_attr_set = 0;
    if (!sa_attr_set) {
        cudaFuncSetAttribute(spatial_attn_wmma_k,
                             cudaFuncAttributeMaxDynamicSharedMemorySize, SA_SMEM);
        sa_attr_set = 1;
    }

    // 1) fp16 conversions
    conv_xc_h<<<(MROWS * 384 + 255) / 256, 256>>>(X, STE, Xh);
    concat_w_h<<<(1536 * 3072 + 255) / 256, 256>>>(sWq, sWk, sWv, tWq, tWk, tWv,
                                                   sbq, sbk, sbv, tbq, tbk, tbv,
                                                   Wch, bcat);
    concat_wg_h<<<(1024 * 512 + 255) / 256, 256>>>(gWxs, gWxt, Wgh);
    conv4_w_h<<<(4 * 262144 + 255) / 256, 256>>>(sWo, tWo, gWh1, gWh2,
                                                 sWoh, tWoh, Wh1h, Wh2h);

    // 2) six projections in one GEMM: Ph = relu(Xh @ Wch + bcat)
    gemm_hh_k<1, __half><<<dim3(24, 192), 256>>>(Xh, Wch, bcat, nullptr, Ph,
                                                 MROWS, 3072, 1536, 1536, 3072, 3072, 0);

    // 3) attention
    spatial_attn_wmma_k<<<dim3(4, NH, BB * TT), 256, SA_SMEM>>>(Ph, HSh);
    temporal_attn_k<<<dim3(NN, BB), 192>>>(Ph, HTh);

    // 4) output projections into HSTh = [relu(HS@sWo+b) | relu(HT@tWo+b)]
    gemm_hh_k<1, __half><<<dim3(4, 192), 256>>>(HSh, sWoh, sbo, nullptr, HSTh,
                                                MROWS, 512, 512, 512, 512, 1024, 0);
    gemm_hh_k<1, __half><<<dim3(4, 192), 256>>>(HTh, tWoh, tbo, nullptr, HSTh + 512,
                                                MROWS, 512, 512, 512, 512, 1024, 0);

    // 5) gated fusion fused in epilogue: H1 = sig(HST@Wg+b)*HSp + (1-sig)*HTp -> HSh
    gemm_hh_k<3, __half><<<dim3(4, 192), 256>>>(HSTh, Wgh, gbxt, HSTh, HSh,
                                                MROWS, 512, 1024, 1024, 512, 512, 1024);

    // 6) MLP: H2 = relu(H1 @ gWh1 + gbh1) -> HTh
    gemm_hh_k<1, __half><<<dim3(4, 192), 256>>>(HSh, Wh1h, gbh1, nullptr, HTh,
                                                MROWS, 512, 512, 512, 512, 512, 0);
    // out = X + H2 @ gWh2 + gbh2   (fp32 out)
    gemm_hh_k<2, float><<<dim3(4, 192), 256>>>(HTh, Wh2h, gbh2, X, out,
                                               MROWS, 512, 512, 512, 512, 512, 512);
}

// round 9
// speedup vs baseline: 5.1567x; 1.0195x over previous
#include <cuda_runtime.h>
#include <cuda_fp16.h>
#include <cstdint>
#include <mma.h>
using namespace nvcuda;

// ---------------- problem constants ----------------
#define BB 2
#define TT 24
#define NN 512
#define DD 512
#define NH 8
#define HD 64
#define MROWS (BB*TT*NN)      // 24576
#define C3 3072               // P row stride: [sQ sK sV tQ tK tV]

// ---------------- scratch (static device globals; no allocation) ----------------
__device__ __half g_Xh [(size_t)MROWS * 1536];   // concat(X, STE) fp16
__device__ __half g_Ph [(size_t)MROWS * 3072];   // six projections, relu'd, fp16
__device__ __half g_Wch[1536 * 3072];
__device__ float  g_bcat[3072];
__device__ __half g_Wgh[1024 * 512];
__device__ __half g_sWoh[512 * 512];
__device__ __half g_tWoh[512 * 512];
__device__ __half g_Wh1h[512 * 512];
__device__ __half g_Wh2h[512 * 512];
__device__ __half g_HSh [(size_t)MROWS * 512];
__device__ __half g_HTh [(size_t)MROWS * 512];
__device__ __half g_HSTh[(size_t)MROWS * 1024];

__device__ __forceinline__ uint2 f4_to_h4(float4 v) {
    __half2 a = __floats2half2_rn(v.x, v.y);
    __half2 b = __floats2half2_rn(v.z, v.w);
    uint2 r;
    r.x = *(unsigned*)&a;
    r.y = *(unsigned*)&b;
    return r;
}

__device__ __forceinline__ void h8_to_f8(uint4 u, float* f) {
    __half2* h = (__half2*)&u;
#pragma unroll
    for (int i = 0; i < 4; i++) {
        float2 t = __half22float2(h[i]);
        f[2 * i] = t.x; f[2 * i + 1] = t.y;
    }
}

#define CP_ASYNC16(dst, src) \
    asm volatile("cp.async.cg.shared.global [%0], [%1], 16;\n" :: "r"(dst), "l"(src))
#define CP_COMMIT() asm volatile("cp.async.commit_group;\n")
#define CP_WAIT(n)  asm volatile("cp.async.wait_group %0;\n" :: "n"(n))

// ---------------- conversion kernels ----------------
__global__ void conv_xc_h(const float* __restrict__ X, const float* __restrict__ STE,
                          __half* __restrict__ Xh)
{
    int idx = blockIdx.x * blockDim.x + threadIdx.x;   // float4 units
    if (idx >= MROWS * 384) return;
    int m = idx / 384, c4 = idx % 384;
    float4 v;
    if (c4 < 128) v = ((const float4*)X)[(size_t)m * 128 + c4];
    else          v = ((const float4*)STE)[(size_t)m * 256 + (c4 - 128)];
    *(uint2*)(Xh + (size_t)idx * 4) = f4_to_h4(v);
}

// one kernel converts/concats ALL weights + bias vector
#define PW_R1 1179648                 // Wch quads (1536 * 768)
#define PW_R2 (PW_R1 + 131072)        // + Wg quads
#define PW_R3 (PW_R2 + 262144)        // + 4x small-W quads
#define PW_R4 (PW_R3 + 768)           // + bcat quads
__global__ void prep_weights_k(
    const float* __restrict__ w0, const float* __restrict__ w1,
    const float* __restrict__ w2, const float* __restrict__ w3,
    const float* __restrict__ w4, const float* __restrict__ w5,
    const float* __restrict__ b0, const float* __restrict__ b1,
    const float* __restrict__ b2, const float* __restrict__ b3,
    const float* __restrict__ b4, const float* __restrict__ b5,
    const float* __restrict__ wxs, const float* __restrict__ wxt,
    const float* __restrict__ sWo, const float* __restrict__ tWo,
    const float* __restrict__ wh1, const float* __restrict__ wh2,
    __half* __restrict__ Wch, __half* __restrict__ Wgh,
    __half* __restrict__ sWoh, __half* __restrict__ tWoh,
    __half* __restrict__ Wh1h, __half* __restrict__ Wh2h,
    float* __restrict__ bcat)
{
    int idx = blockIdx.x * blockDim.x + threadIdx.x;
    if (idx < PW_R1) {
        int k = idx / 768, q = idx % 768;
        int j = q >> 7, cq = q & 127;
        const float* ws[6] = {w0, w1, w2, w3, w4, w5};
        float4 v = *(const float4*)(ws[j] + k * 512 + cq * 4);
        *(uint2*)(Wch + (size_t)k * 3072 + j * 512 + cq * 4) = f4_to_h4(v);
    } else if (idx < PW_R2) {
        int e = idx - PW_R1;            // quad over [1024][128]
        int k = e >> 7, cq = e & 127;
        const float* src = (k < 512) ? (wxs + k * 512) : (wxt + (k - 512) * 512);
        float4 v = *(const float4*)(src + cq * 4);
        *(uint2*)(Wgh + (size_t)k * 512 + cq * 4) = f4_to_h4(v);
    } else if (idx < PW_R3) {
        int e = idx - PW_R2;            // 4 x 65536 quads
        int which = e >> 16, q = e & 65535;
        const float* w = (which == 0) ? sWo : (which == 1) ? tWo : (which == 2) ? wh1 : wh2;
        __half* o = (which == 0) ? sWoh : (which == 1) ? tWoh : (which == 2) ? Wh1h : Wh2h;
        float4 v = *(const float4*)(w + q * 4);
        *(uint2*)(o + (size_t)q * 4) = f4_to_h4(v);
    } else if (idx < PW_R4) {
        int e = idx - PW_R3;            // 768 quads of bcat
        int j = e >> 7, c = e & 127;
        const float* bs[6] = {b0, b1, b2, b3, b4, b5};
        *(float4*)(bcat + j * 512 + c * 4) = *(const float4*)(bs[j] + c * 4);
    }
}

// ---------------- fp16 tensor GEMM 128x128, BK=32, 4-stage cp.async ----------------
// ACT: 0 bias, 1 bias+relu, 2 bias+residual(float R), 3 gated fusion(half R)
#define GA_LDH 40
#define GB_LDH 136
#define GAS (128 * GA_LDH)   // 5120 halves / stage
#define GBS (32 * GB_LDH)    // 4352 halves / stage
#define NSTAGE 4
#define GSMEM_DYN (NSTAGE * (GAS + GBS) * 2)   // 75776 B

template<int ACT, typename OutT>
__global__ void __launch_bounds__(256, 2) gemm_cp_k(
    const __half* __restrict__ A, const __half* __restrict__ B,
    const float* __restrict__ bias, const void* __restrict__ Rv,
    OutT* __restrict__ C, int M, int N, int K, int lda, int ldb, int ldc, int ldr)
{
    extern __shared__ __align__(16) char dsmem[];
    __half* As = (__half*)dsmem;
    __half* Bs = (__half*)dsmem + NSTAGE * GAS;

    const int tid  = threadIdx.x;
    const int warp = tid >> 5;
    const int lane = tid & 31;
    const int wm   = warp & 3;
    const int wn   = warp >> 2;
    const int m0 = blockIdx.y * 128;
    const int n0 = blockIdx.x * 128;

    const int a_row = tid >> 2;          // 0..63 (two rows per thread)
    const int a_c8  = (tid & 3) << 3;
    const int b_row = tid >> 4;          // 0..15 (two rows per thread)
    const int b_c8  = (tid & 15) << 3;

    const unsigned int sA = (unsigned int)__cvta_generic_to_shared(As);
    const unsigned int sB = (unsigned int)__cvta_generic_to_shared(Bs);

    const int nk = K >> 5;

    // async copy one BK=32 stage
    auto issue = [&](int kt, int stage) {
        int k0 = kt << 5;
        CP_ASYNC16(sA + (stage * GAS + a_row * GA_LDH + a_c8) * 2,
                   A + (size_t)(m0 + a_row) * lda + k0 + a_c8);
        CP_ASYNC16(sA + (stage * GAS + (64 + a_row) * GA_LDH + a_c8) * 2,
                   A + (size_t)(m0 + 64 + a_row) * lda + k0 + a_c8);
        CP_ASYNC16(sB + (stage * GBS + b_row * GB_LDH + b_c8) * 2,
                   B + (size_t)(k0 + b_row) * ldb + n0 + b_c8);
        CP_ASYNC16(sB + (stage * GBS + (16 + b_row) * GB_LDH + b_c8) * 2,
                   B + (size_t)(k0 + 16 + b_row) * ldb + n0 + b_c8);
    };

    wmma::fragment<wmma::accumulator, 16, 16, 16, float> acc[2][4];
#pragma unroll
    for (int i = 0; i < 2; i++)
#pragma unroll
        for (int j = 0; j < 4; j++) wmma::fill_fragment(acc[i][j], 0.f);

#pragma unroll
    for (int s = 0; s < NSTAGE - 1; s++) {
        if (s < nk) issue(s, s);
        CP_COMMIT();
    }

    for (int kt = 0; kt < nk; kt++) {
        CP_WAIT(NSTAGE - 2);
        __syncthreads();

        int nx = kt + NSTAGE - 1;
        if (nx < nk) issue(nx, nx & (NSTAGE - 1));
        CP_COMMIT();

        const int buf = kt & (NSTAGE - 1);
        const __half* Ab = As + buf * GAS;
        const __half* Bb = Bs + buf * GBS;
#pragma unroll
        for (int ks = 0; ks < 2; ks++) {
            wmma::fragment<wmma::matrix_a, 16, 16, 16, __half, wmma::row_major> af[2];
#pragma unroll
            for (int fm = 0; fm < 2; fm++)
                wmma::load_matrix_sync(af[fm], Ab + (wm * 32 + fm * 16) * GA_LDH + ks * 16, GA_LDH);
#pragma unroll
            for (int fn = 0; fn < 4; fn++) {
                wmma::fragment<wmma::matrix_b, 16, 16, 16, __half, wmma::row_major> bf;
                wmma::load_matrix_sync(bf, Bb + (ks * 16) * GB_LDH + wn * 64 + fn * 16, GB_LDH);
#pragma unroll
                for (int fm = 0; fm < 2; fm++)
                    wmma::mma_sync(acc[fm][fn], af[fm], bf, acc[fm][fn]);
            }
        }
    }
    CP_WAIT(0);
    __syncthreads();

    // epilogue via per-warp fp32 scratch (32 rows x 40 stride)
    float* sw = (float*)dsmem + warp * (32 * 40);
#pragma unroll
    for (int h = 0; h < 2; h++) {
#pragma unroll
        for (int fm = 0; fm < 2; fm++)
#pragma unroll
            for (int fnl = 0; fnl < 2; fnl++)
                wmma::store_matrix_sync(sw + fm * 16 * 40 + fnl * 16,
                                        acc[fm][h * 2 + fnl], 40, wmma::mem_row_major);
        __syncwarp();
        const int colbase = n0 + wn * 64 + h * 32;
#pragma unroll
        for (int i = 0; i < 8; i++) {
            int idx = lane + i * 32;
            int r  = idx >> 3;
            int c4 = (idx & 7) << 2;
            float4 v = *(float4*)(sw + r * 40 + c4);
            int row = m0 + wm * 32 + r;
            int col = colbase + c4;
            float4 bv = *(const float4*)(bias + col);
            v.x += bv.x; v.y += bv.y; v.z += bv.z; v.w += bv.w;
            if (ACT == 1) {
                v.x = fmaxf(v.x, 0.f); v.y = fmaxf(v.y, 0.f);
                v.z = fmaxf(v.z, 0.f); v.w = fmaxf(v.w, 0.f);
            }
            if (ACT == 2) {
                const float* Rf = (const float*)Rv;
                float4 rv = *(const float4*)(Rf + (size_t)row * ldr + col);
                v.x += rv.x; v.y += rv.y; v.z += rv.z; v.w += rv.w;
            }
            if (ACT == 3) {
                const __half* Rh = (const __half*)Rv;
                float hs[4], ht[4];
                uint2 u1 = *(const uint2*)(Rh + (size_t)row * ldr + col);
                uint2 u2 = *(const uint2*)(Rh + (size_t)row * ldr + 512 + col);
                {
                    __half2* hh = (__half2*)&u1;
                    float2 t0 = __half22float2(hh[0]), t1 = __half22float2(hh[1]);
                    hs[0] = t0.x; hs[1] = t0.y; hs[2] = t1.x; hs[3] = t1.y;
                }
                {
                    __half2* hh = (__half2*)&u2;
                    float2 t0 = __half22float2(hh[0]), t1 = __half22float2(hh[1]);
                    ht[0] = t0.x; ht[1] = t0.y; ht[2] = t1.x; ht[3] = t1.y;
                }
                float zx = 1.f / (1.f + __expf(-v.x));
                float zy = 1.f / (1.f + __expf(-v.y));
                float zz = 1.f / (1.f + __expf(-v.z));
                float zw = 1.f / (1.f + __expf(-v.w));
                v.x = zx * hs[0] + (1.f - zx) * ht[0];
                v.y = zy * hs[1] + (1.f - zy) * ht[1];
                v.z = zz * hs[2] + (1.f - zz) * ht[2];
                v.w = zw * hs[3] + (1.f - zw) * ht[3];
            }
            if constexpr (sizeof(OutT) == 2) {
                *(uint2*)((__half*)C + (size_t)row * ldc + col) = f4_to_h4(v);
            } else {
                *(float4*)((float*)C + (size_t)row * ldc + col) = v;
            }
        }
        __syncwarp();
    }
}

// ---------------- spatial attention: wmma flash (fp16 P) ----------------
#define SA_QS_OFF   0
#define SA_KS_OFF   18432
#define SA_VS_OFF   (18432 + 9216)
#define SA_SC_OFF   36864
#define SA_PS_OFF   (36864 + 34816)
#define SA_SMEM     90112

__global__ void __launch_bounds__(256, 2) spatial_attn_wmma_k(const __half* __restrict__ P,
                                                              __half* __restrict__ HS)
{
    extern __shared__ __align__(16) char dsm[];
    __half* Qs = (__half*)(dsm + SA_QS_OFF);
    __half* Ks = (__half*)(dsm + SA_KS_OFF);
    __half* Vs = (__half*)(dsm + SA_VS_OFF);
    float*  Sc = (float*)(dsm + SA_SC_OFF);
    __half* Ps = (__half*)(dsm + SA_PS_OFF);

    const int tid  = threadIdx.x;
    const int w    = tid >> 5;
    const int lane = tid & 31;
    const int q0   = blockIdx.x * 128;
    const int h    = blockIdx.y;
    const int bt   = blockIdx.z;

    const __half* base = P + (size_t)bt * NN * C3;

    for (int idx = tid; idx < 1024; idx += 256) {
        int row = idx >> 3, c8 = (idx & 7) << 3;
        *(uint4*)(Qs + row * 72 + c8) =
            *(const uint4*)(base + (size_t)(q0 + row) * C3 + h * HD + c8);
    }
    __syncthreads();

    wmma::fragment<wmma::matrix_a, 16, 16, 16, __half, wmma::row_major> qf[4];
#pragma unroll
    for (int i = 0; i < 4; i++)
        wmma::load_matrix_sync(qf[i], Qs + (w * 16) * 72 + i * 16, 72);

    float* Sw  = Sc + w * 1088;
    __half* Pw = Ps + w * 1152;
    const int r  = lane >> 1;
    const int hf = lane & 1;

    float Oreg[32];
#pragma unroll
    for (int i = 0; i < 32; i++) Oreg[i] = 0.f;
    float m = -1e30f, l = 0.f;

    for (int tile = 0; tile < 8; tile++) {
        __syncthreads();
        for (int idx = tid; idx < 512; idx += 256) {
            int row = idx >> 3, c8 = (idx & 7) << 3;
            const __half* rp = base + (size_t)(tile * 64 + row) * C3 + h * HD + c8;
            *(uint4*)(Ks + row * 72 + c8) = *(const uint4*)(rp + 512);
            *(uint4*)(Vs + row * 72 + c8) = *(const uint4*)(rp + 1024);
        }
        __syncthreads();

        wmma::fragment<wmma::accumulator, 16, 16, 16, float> sf[4];
#pragma unroll
        for (int j = 0; j < 4; j++) wmma::fill_fragment(sf[j], 0.f);
#pragma unroll
        for (int i = 0; i < 4; i++) {
#pragma unroll
            for (int j = 0; j < 4; j++) {
                wmma::fragment<wmma::matrix_b, 16, 16, 16, __half, wmma::col_major> bf;
                wmma::load_matrix_sync(bf, Ks + (j * 16) * 72 + i * 16, 72);
                wmma::mma_sync(sf[j], qf[i], bf, sf[j]);
            }
        }
#pragma unroll
        for (int j = 0; j < 4; j++)
            wmma::store_matrix_sync(Sw + j * 16, sf[j], 68, wmma::mem_row_major);
        __syncwarp();

        const float* srow = Sw + r * 68 + hf * 32;
        float mx = -1e30f;
#pragma unroll
        for (int j = 0; j < 32; j++) mx = fmaxf(mx, srow[j]);
        mx = fmaxf(mx, __shfl_xor_sync(0xffffffffu, mx, 1));
        float tm = mx * 0.125f;
        float nm = fmaxf(m, tm);
        float rf = __expf(m - nm);
#pragma unroll
        for (int j = 0; j < 32; j++) Oreg[j] *= rf;
        float ps = 0.f;
        __half* prow = Pw + r * 72 + hf * 32;
#pragma unroll
        for (int j = 0; j < 32; j += 2) {
            float p0 = __expf(srow[j] * 0.125f - nm);
            float p1 = __expf(srow[j + 1] * 0.125f - nm);
            ps += p0 + p1;
            *(__half2*)(prow + j) = __floats2half2_rn(p0, p1);
        }
        ps += __shfl_xor_sync(0xffffffffu, ps, 1);
        l = l * rf + ps;
        m = nm;
        __syncwarp();

        wmma::fragment<wmma::accumulator, 16, 16, 16, float> of[4];
#pragma unroll
        for (int j = 0; j < 4; j++) wmma::fill_fragment(of[j], 0.f);
#pragma unroll
        for (int i = 0; i < 4; i++) {
            wmma::fragment<wmma::matrix_a, 16, 16, 16, __half, wmma::row_major> af;
            wmma::load_matrix_sync(af, Pw + i * 16, 72);
#pragma unroll
            for (int j = 0; j < 4; j++) {
                wmma::fragment<wmma::matrix_b, 16, 16, 16, __half, wmma::row_major> bf;
                wmma::load_matrix_sync(bf, Vs + (i * 16) * 72 + j * 16, 72);
                wmma::mma_sync(of[j], af, bf, of[j]);
            }
        }
#pragma unroll
        for (int j = 0; j < 4; j++)
            wmma::store_matrix_sync(Sw + j * 16, of[j], 68, wmma::mem_row_major);
        __syncwarp();
        const float* orow = Sw + r * 68 + hf * 32;
#pragma unroll
        for (int j = 0; j < 32; j++) Oreg[j] += orow[j];
        __syncwarp();
    }

    float inv = 1.f / l;
    __half* op = HS + (size_t)(bt * NN + q0 + w * 16 + r) * 512 + h * HD + hf * 32;
#pragma unroll
    for (int i = 0; i < 8; i++) {
        float4 v = make_float4(Oreg[4 * i] * inv, Oreg[4 * i + 1] * inv,
                               Oreg[4 * i + 2] * inv, Oreg[4 * i + 3] * inv);
        *(uint2*)(op + i * 4) = f4_to_h4(v);
    }
}

// ---------------- temporal attention (causal over T=24, fp16 P) ----------------
__global__ void __launch_bounds__(192) temporal_attn_k(const __half* __restrict__ P,
                                                       __half* __restrict__ HT)
{
    const int n = blockIdx.x;
    const int b = blockIdx.y;
    const int h = threadIdx.x & 7;
    const int t = threadIdx.x >> 3;

    float q[64];
    {
        const uint4* qp = (const uint4*)(P + ((size_t)(b * TT + t) * NN + n) * C3 + 1536 + h * HD);
#pragma unroll
        for (int i = 0; i < 8; i++) h8_to_f8(__ldg(qp + i), q + 8 * i);
    }
    float o[64];
#pragma unroll
    for (int i = 0; i < 64; i++) o[i] = 0.f;
    float mr = -1e30f, l = 0.f;

    for (int s = 0; s <= t; s++) {
        size_t rk = ((size_t)(b * TT + s) * NN + n) * C3;
        const uint4* kp = (const uint4*)(P + rk + 2048 + h * HD);
        const uint4* vp = (const uint4*)(P + rk + 2560 + h * HD);
        float kb[64];
#pragma unroll
        for (int i = 0; i < 8; i++) h8_to_f8(__ldg(kp + i), kb + 8 * i);
        float s0 = 0.f, s1 = 0.f, s2 = 0.f, s3 = 0.f;
#pragma unroll
        for (int c = 0; c < 16; c++) {
            s0 += q[4 * c]     * kb[4 * c];
            s1 += q[4 * c + 1] * kb[4 * c + 1];
            s2 += q[4 * c + 2] * kb[4 * c + 2];
            s3 += q[4 * c + 3] * kb[4 * c + 3];
        }
        float sc = ((s0 + s1) + (s2 + s3)) * 0.125f;
        float vb[64];
#pragma unroll
        for (int i = 0; i < 8; i++) h8_to_f8(__ldg(vp + i), vb + 8 * i);
        if (sc <= mr) {
            float p = __expf(sc - mr);
            l += p;
#pragma unroll
            for (int c = 0; c < 64; c++) o[c] += p * vb[c];
        } else {
            float r = __expf(mr - sc);
            mr = sc;
            l = l * r + 1.f;
#pragma unroll
            for (int c = 0; c < 64; c++) o[c] = o[c] * r + vb[c];
        }
    }
    float inv = 1.f / l;
    __half* op = HT + ((size_t)(b * TT + t) * NN + n) * 512 + h * HD;
#pragma unroll
    for (int i = 0; i < 16; i++) {
        float4 v = make_float4(o[4 * i] * inv, o[4 * i + 1] * inv,
                               o[4 * i + 2] * inv, o[4 * i + 3] * inv);
        *(uint2*)(op + 4 * i) = f4_to_h4(v);
    }
}

// ---------------- launch ----------------
extern "C" void kernel_launch(void* const* d_in, const int* in_sizes, int n_in,
                              void* d_out, int out_size)
{
    const float* X    = (const float*)d_in[0];
    const float* STE  = (const float*)d_in[1];
    const float* sWq  = (const float*)d_in[2];
    const float* sbq  = (const float*)d_in[3];
    const float* sWk  = (const float*)d_in[4];
    const float* sbk  = (const float*)d_in[5];
    const float* sWv  = (const float*)d_in[6];
    const float* sbv  = (const float*)d_in[7];
    const float* sWo  = (const float*)d_in[8];
    const float* sbo  = (const float*)d_in[9];
    const float* tWq  = (const float*)d_in[10];
    const float* tbq  = (const float*)d_in[11];
    const float* tWk  = (const float*)d_in[12];
    const float* tbk  = (const float*)d_in[13];
    const float* tWv  = (const float*)d_in[14];
    const float* tbv  = (const float*)d_in[15];
    const float* tWo  = (const float*)d_in[16];
    const float* tbo  = (const float*)d_in[17];
    const float* gWxs = (const float*)d_in[18];
    const float* gWxt = (const float*)d_in[19];
    const float* gbxt = (const float*)d_in[20];
    const float* gWh1 = (const float*)d_in[21];
    const float* gbh1 = (const float*)d_in[22];
    const float* gWh2 = (const float*)d_in[23];
    const float* gbh2 = (const float*)d_in[24];
    float* out = (float*)d_out;

    __half *Xh, *Ph, *Wch, *Wgh, *sWoh, *tWoh, *Wh1h, *Wh2h, *HSh, *HTh, *HSTh;
    float *bcat;
    cudaGetSymbolAddress((void**)&Xh,   g_Xh);
    cudaGetSymbolAddress((void**)&Ph,   g_Ph);
    cudaGetSymbolAddress((void**)&Wch,  g_Wch);
    cudaGetSymbolAddress((void**)&bcat, g_bcat);
    cudaGetSymbolAddress((void**)&Wgh,  g_Wgh);
    cudaGetSymbolAddress((void**)&sWoh, g_sWoh);
    cudaGetSymbolAddress((void**)&tWoh, g_tWoh);
    cudaGetSymbolAddress((void**)&Wh1h, g_Wh1h);
    cudaGetSymbolAddress((void**)&Wh2h, g_Wh2h);
    cudaGetSymbolAddress((void**)&HSh,  g_HSh);
    cudaGetSymbolAddress((void**)&HTh,  g_HTh);
    cudaGetSymbolAddress((void**)&HSTh, g_HSTh);

    static int attr_set = 0;
    if (!attr_set) {
        cudaFuncSetAttribute(spatial_attn_wmma_k,
                             cudaFuncAttributeMaxDynamicSharedMemorySize, SA_SMEM);
        cudaFuncSetAttribute(gemm_cp_k<1, __half>,
                             cudaFuncAttributeMaxDynamicSharedMemorySize, GSMEM_DYN);
        cudaFuncSetAttribute(gemm_cp_k<3, __half>,
                             cudaFuncAttributeMaxDynamicSharedMemorySize, GSMEM_DYN);
        cudaFuncSetAttribute(gemm_cp_k<2, float>,
                             cudaFuncAttributeMaxDynamicSharedMemorySize, GSMEM_DYN);
        attr_set = 1;
    }

    // 1) fp16 conversions
    conv_xc_h<<<(MROWS * 384 + 255) / 256, 256>>>(X, STE, Xh);
    prep_weights_k<<<(PW_R4 + 255) / 256, 256>>>(
        sWq, sWk, sWv, tWq, tWk, tWv,
        sbq, sbk, sbv, tbq, tbk, tbv,
        gWxs, gWxt, sWo, tWo, gWh1, gWh2,
        Wch, Wgh, sWoh, tWoh, Wh1h, Wh2h, bcat);

    // 2) six projections in one GEMM: Ph = relu(Xh @ Wch + bcat)
    gemm_cp_k<1, __half><<<dim3(24, 192), 256, GSMEM_DYN>>>(
        Xh, Wch, bcat, nullptr, Ph, MROWS, 3072, 1536, 1536, 3072, 3072, 0);

    // 3) attention
    spatial_attn_wmma_k<<<dim3(4, NH, BB * TT), 256, SA_SMEM>>>(Ph, HSh);
    temporal_attn_k<<<dim3(NN, BB), 192>>>(Ph, HTh);

    // 4) output projections into HSTh = [relu(HS@sWo+b) | relu(HT@tWo+b)]
    gemm_cp_k<1, __half><<<dim3(4, 192), 256, GSMEM_DYN>>>(
        HSh, sWoh, sbo, nullptr, HSTh, MROWS, 512, 512, 512, 512, 1024, 0);
    gemm_cp_k<1, __half><<<dim3(4, 192), 256, GSMEM_DYN>>>(
        HTh, tWoh, tbo, nullptr, HSTh + 512, MROWS, 512, 512, 512, 512, 1024, 0);

    // 5) gated fusion fused in epilogue: H1 = sig(HST@Wg+b)*HSp + (1-sig)*HTp -> HSh
    gemm_cp_k<3, __half><<<dim3(4, 192), 256, GSMEM_DYN>>>(
        HSTh, Wgh, gbxt, HSTh, HSh, MROWS, 512, 1024, 1024, 512, 512, 1024);

    // 6) MLP: H2 = relu(H1 @ gWh1 + gbh1) -> HTh
    gemm_cp_k<1, __half><<<dim3(4, 192), 256, GSMEM_DYN>>>(
        HSh, Wh1h, gbh1, nullptr, HTh, MROWS, 512, 512, 512, 512, 512, 0);
    // out = X + H2 @ gWh2 + gbh2   (fp32 out)
    gemm_cp_k<2, float><<<dim3(4, 192), 256, GSMEM_DYN>>>(
        HTh, Wh2h, gbh2, X, out, MROWS, 512, 512, 512, 512, 512, 512);
}